// round 8
// baseline (speedup 1.0000x reference)
#include <cuda_runtime.h>

// ---------------------------------------------------------------------------
// Problem constants
// ---------------------------------------------------------------------------
constexpr int P_ = 2;           // two pipelines (points1/points2)
constexpr int B_ = 2;           // batch per pipeline
constexpr int NI = P_ * B_;     // 4 independent instances
constexpr int N0 = 8192;        // input points
constexpr int C0 = 10;          // input feature channels
constexpr int S1 = 4096;        // SA1 npoint
constexpr int S2 = 1024;        // SA2 npoint

// ---------------------------------------------------------------------------
// Scratch (static device globals — no allocation allowed)
// ---------------------------------------------------------------------------
__device__ float d_pts [NI * N0 * 3];
__device__ float d_fea [NI * N0 * C0];
__device__ int   d_fps1[NI * S1];
__device__ float d_l1x [NI * S1 * 3];
__device__ int   d_gidx1[NI * S1 * 16];
__device__ float d_h1a [NI * S1 * 16 * 16];
__device__ float d_h1b [NI * S1 * 16 * 32];
__device__ float d_l1f [NI * S1 * 32];
__device__ int   d_fps2[NI * S2];
__device__ float d_l2x [NI * S2 * 3];
__device__ int   d_gidx2[NI * S2 * 16];
__device__ float d_h2a [NI * S2 * 16 * 32];
__device__ float d_h2b [NI * S2 * 16 * 64];
__device__ float d_l2f [NI * S2 * 64];
__device__ int   d_suidx[NI * S1 * 8];
__device__ float d_hsu [NI * S1 * 8 * 32];
__device__ float d_hcat[NI * S1 * 64];
__device__ float d_l1n [NI * S1 * 32];
__device__ float d_fph [NI * N0 * 42];
__device__ float d_l0n [NI * N0 * 32];
__device__ float d_acc [1088];   // BN accumulators for all 8 BN sites

// BN accumulator slot offsets (each slot holds P_*2*C floats)
constexpr int SL_SA1A = 0;     // C=16
constexpr int SL_SA1B = 64;    // C=32
constexpr int SL_SA2A = 192;   // C=32
constexpr int SL_SA2B = 320;   // C=64
constexpr int SL_SU1  = 576;   // C=32
constexpr int SL_SU2  = 704;   // C=32
constexpr int SL_FP   = 832;   // C=32
constexpr int SL_BN1  = 960;   // C=32

// ---------------------------------------------------------------------------
// Helpers
// ---------------------------------------------------------------------------
__device__ __forceinline__ float sumsq3(float x, float y, float z) {
    // strict mul/add — matches XLA elementwise+reduce fusion (no fma)
    return __fadd_rn(__fadd_rn(__fmul_rn(x, x), __fmul_rn(y, y)), __fmul_rn(z, z));
}
__device__ __forceinline__ float expdist(float qx, float qy, float qz, float qq,
                                         float px, float py, float pz, float pp) {
    // dot product via fma chain — matches Eigen dot_general K-loop (fma accumulate)
    float dot = fmaf(qz, pz, fmaf(qy, py, __fmul_rn(qx, px)));
    return __fsub_rn(__fadd_rn(qq, pp), __fmul_rn(2.0f, dot));
}
template <int KK>
__device__ __forceinline__ void topk_insert(float d, int j, float* bd, int* bi) {
    if (d < bd[KK - 1] || (d == bd[KK - 1] && j < bi[KK - 1])) {
        bd[KK - 1] = d; bi[KK - 1] = j;
#pragma unroll
        for (int t = KK - 1; t > 0; t--) {
            if (bd[t] < bd[t - 1] || (bd[t] == bd[t - 1] && bi[t] < bi[t - 1])) {
                float td = bd[t]; bd[t] = bd[t - 1]; bd[t - 1] = td;
                int   ti = bi[t]; bi[t] = bi[t - 1]; bi[t - 1] = ti;
            }
        }
    }
}

// ---------------------------------------------------------------------------
// Init: pack inputs into per-instance buffers, zero BN accumulators
// ---------------------------------------------------------------------------
__global__ void k_init(const float* __restrict__ p1, const float* __restrict__ f1,
                       const float* __restrict__ p2, const float* __restrict__ f2) {
    int i = blockIdx.x * blockDim.x + threadIdx.x;
    if (i < NI * N0 * 3)
        d_pts[i] = (i < B_ * N0 * 3) ? p1[i] : p2[i - B_ * N0 * 3];
    if (i < NI * N0 * C0)
        d_fea[i] = (i < B_ * N0 * C0) ? f1[i] : f2[i - B_ * N0 * C0];
    if (i < 1088) d_acc[i] = 0.0f;
}

// ---------------------------------------------------------------------------
// Farthest point sampling: one 1024-thread block per instance.
// ---------------------------------------------------------------------------
template <int NPT>
__global__ void __launch_bounds__(1024) k_fps(const float* __restrict__ ptsAll,
                                              int N, int npoint,
                                              int* __restrict__ idxAll,
                                              float* __restrict__ nxyzAll) {
    const int T = 1024;
    int inst = blockIdx.x;
    const float* xyz = ptsAll + inst * N * 3;
    int*   idx_out = idxAll + inst * npoint;
    float* nxyz    = nxyzAll + inst * npoint * 3;

    extern __shared__ float sm[];
    float* sx = sm; float* sy = sm + N; float* sz = sm + 2 * N;
    __shared__ float s_rv[32];
    __shared__ int   s_ri[32];
    __shared__ float s_c[3];

    int tid = threadIdx.x;
    int lane = tid & 31, wid = tid >> 5;

    float px[NPT], py[NPT], pz[NPT], dd[NPT];
#pragma unroll
    for (int u = 0; u < NPT; u++) {
        int j = tid + u * T;
        px[u] = xyz[3 * j]; py[u] = xyz[3 * j + 1]; pz[u] = xyz[3 * j + 2];
        dd[u] = 1e10f;
        sx[j] = px[u]; sy[j] = py[u]; sz[j] = pz[u];
    }
    if (tid == 0) {
        idx_out[0] = 0;
        s_c[0] = xyz[0]; s_c[1] = xyz[1]; s_c[2] = xyz[2];
    }

    for (int i = 0; i < npoint - 1; i++) {
        __syncthreads();
        float cx = s_c[0], cy = s_c[1], cz = s_c[2];
        float bv = -1.0f; int bi = 0;
#pragma unroll
        for (int u = 0; u < NPT; u++) {
            float dx = __fsub_rn(px[u], cx);
            float dy = __fsub_rn(py[u], cy);
            float dz = __fsub_rn(pz[u], cz);
            float d = sumsq3(dx, dy, dz);
            float nd = fminf(dd[u], d);
            dd[u] = nd;
            if (nd > bv) { bv = nd; bi = tid + u * T; }
        }
#pragma unroll
        for (int off = 16; off > 0; off >>= 1) {
            float ov = __shfl_down_sync(0xffffffffu, bv, off);
            int   oi = __shfl_down_sync(0xffffffffu, bi, off);
            if (ov > bv || (ov == bv && oi < bi)) { bv = ov; bi = oi; }
        }
        if (lane == 0) { s_rv[wid] = bv; s_ri[wid] = bi; }
        __syncthreads();
        if (wid == 0) {
            bv = s_rv[lane]; bi = s_ri[lane];
#pragma unroll
            for (int off = 16; off > 0; off >>= 1) {
                float ov = __shfl_down_sync(0xffffffffu, bv, off);
                int   oi = __shfl_down_sync(0xffffffffu, bi, off);
                if (ov > bv || (ov == bv && oi < bi)) { bv = ov; bi = oi; }
            }
            if (lane == 0) {
                idx_out[i + 1] = bi;
                s_c[0] = sx[bi]; s_c[1] = sy[bi]; s_c[2] = sz[bi];
            }
        }
    }
    __syncthreads();
    for (int s = tid; s < npoint; s += T) {
        int id = idx_out[s];
        nxyz[3 * s] = sx[id]; nxyz[3 * s + 1] = sy[id]; nxyz[3 * s + 2] = sz[id];
    }
}

// ---------------------------------------------------------------------------
// Ball query: first 16 in-range indices (== 16 smallest) + nearest fallback
// ---------------------------------------------------------------------------
__global__ void k_ballquery(const float* __restrict__ ptsAll, const float* __restrict__ qAll,
                            int N, int S, float r2, int* __restrict__ gidxAll) {
    extern __shared__ float sm[];
    float* sx = sm; float* sy = sm + N; float* sz = sm + 2 * N; float* sp = sm + 3 * N;
    int inst = blockIdx.y;
    const float* pts = ptsAll + inst * N * 3;
    for (int j = threadIdx.x; j < N; j += blockDim.x) {
        float x = pts[3 * j], y = pts[3 * j + 1], z = pts[3 * j + 2];
        sx[j] = x; sy[j] = y; sz[j] = z;
        sp[j] = sumsq3(x, y, z);
    }
    __syncthreads();
    int q = blockIdx.x * blockDim.x + threadIdx.x;
    if (q >= S) return;
    const float* nq = qAll + (inst * S + q) * 3;
    float qx = nq[0], qy = nq[1], qz = nq[2];
    float qq = sumsq3(qx, qy, qz);

    int res[16]; int cnt = 0;
    float dmin = 3.402823466e38f; int jmin = 0;
    for (int j = 0; j < N; j++) {
        float d = expdist(qx, qy, qz, qq, sx[j], sy[j], sz[j], sp[j]);
        if (d < dmin) { dmin = d; jmin = j; }
        if (d <= r2) { res[cnt++] = j; if (cnt == 16) break; }
    }
    int* out = gidxAll + (inst * S + q) * 16;
    if (cnt == 0) {
        for (int k = 0; k < 16; k++) out[k] = jmin;
    } else {
        int f = res[0];
        for (int k = 0; k < 16; k++) out[k] = (k < cnt) ? res[k] : f;
    }
}

// ---------------------------------------------------------------------------
// kNN (k smallest distances, stable tie-break) — set_upconv (k=8)
// ---------------------------------------------------------------------------
template <int KK>
__global__ void k_knn(const float* __restrict__ refAll, const float* __restrict__ qAll,
                      int M, int S, int* __restrict__ outIdx) {
    extern __shared__ float sm[];
    float* sx = sm; float* sy = sm + M; float* sz = sm + 2 * M; float* sp = sm + 3 * M;
    int inst = blockIdx.y;
    const float* ref = refAll + inst * M * 3;
    for (int j = threadIdx.x; j < M; j += blockDim.x) {
        float x = ref[3 * j], y = ref[3 * j + 1], z = ref[3 * j + 2];
        sx[j] = x; sy[j] = y; sz[j] = z;
        sp[j] = sumsq3(x, y, z);
    }
    __syncthreads();
    int q = blockIdx.x * blockDim.x + threadIdx.x;
    if (q >= S) return;
    const float* qp = qAll + (inst * S + q) * 3;
    float qx = qp[0], qy = qp[1], qz = qp[2];
    float qq = sumsq3(qx, qy, qz);
    float bd[KK]; int bi[KK];
#pragma unroll
    for (int k = 0; k < KK; k++) { bd[k] = 3.402823466e38f; bi[k] = 0x7fffffff; }
    for (int j = 0; j < M; j++) {
        float d = expdist(qx, qy, qz, qq, sx[j], sy[j], sz[j], sp[j]);
        topk_insert<KK>(d, j, bd, bi);
    }
    int* o = outIdx + (inst * S + q) * KK;
#pragma unroll
    for (int k = 0; k < KK; k++) o[k] = bi[k];
}

// ---------------------------------------------------------------------------
// SA layer0 matmul with fused grouping: in = [xyz[id]-newxyz, feat[id]]
// ---------------------------------------------------------------------------
template <int CF, int O>
__global__ void k_group_mm(const float* __restrict__ ptsAll, const float* __restrict__ nxyzAll,
                           const float* __restrict__ featAll, const int* __restrict__ gidxAll,
                           const float* __restrict__ w, float* __restrict__ outAll,
                           int N, int S, int rowsTotal) {
    const int CIN = CF + 3;
    __shared__ float sw[O * CIN];
    for (int i = threadIdx.x; i < O * CIN; i += blockDim.x) sw[i] = w[i];
    __syncthreads();
    int g = blockIdx.x * blockDim.x + threadIdx.x;
    if (g >= rowsTotal) return;
    int sk = S * 16;
    int inst = g / sk;
    int rem = g - inst * sk;
    int s = rem >> 4;
    int id = gidxAll[g];
    const float* p = ptsAll + (inst * N + id) * 3;
    const float* nx = nxyzAll + (inst * S + s) * 3;
    float in[CIN];
    in[0] = p[0] - nx[0]; in[1] = p[1] - nx[1]; in[2] = p[2] - nx[2];
    const float* f = featAll + (inst * N + id) * CF;
#pragma unroll
    for (int c = 0; c < CF; c++) in[3 + c] = f[c];
    float* o = outAll + (size_t)g * O;
    for (int oo = 0; oo < O; oo++) {
        float acc = 0.0f;
#pragma unroll
        for (int c = 0; c < CIN; c++) acc = fmaf(in[c], sw[oo * CIN + c], acc);
        o[oo] = acc;
    }
}

// ---------------------------------------------------------------------------
// Dense row matmul
// ---------------------------------------------------------------------------
template <int CIN, int O>
__global__ void k_dense(const float* __restrict__ inAll, const float* __restrict__ w,
                        float* __restrict__ outAll, int rows) {
    __shared__ float sw[O * CIN];
    for (int i = threadIdx.x; i < O * CIN; i += blockDim.x) sw[i] = w[i];
    __syncthreads();
    int g = blockIdx.x * blockDim.x + threadIdx.x;
    if (g >= rows) return;
    float in[CIN];
    const float* src = inAll + (size_t)g * CIN;
#pragma unroll
    for (int c = 0; c < CIN; c++) in[c] = src[c];
    float* o = outAll + (size_t)g * O;
    for (int oo = 0; oo < O; oo++) {
        float acc = 0.0f;
#pragma unroll
        for (int c = 0; c < CIN; c++) acc = fmaf(in[c], sw[oo * CIN + c], acc);
        o[oo] = acc;
    }
}

// ---------------------------------------------------------------------------
// BN reduce (sum, sumsq per channel per pipeline) + apply scale/shift + relu
// ---------------------------------------------------------------------------
template <int C>
__global__ void k_bnreduce(const float* __restrict__ x, int rowsPerP, int slotOff) {
    __shared__ float ss[C], sq[C];
    int tid = threadIdx.x;
    if (tid < C) { ss[tid] = 0.0f; sq[tid] = 0.0f; }
    __syncthreads();
    int p = blockIdx.z;
    const float* base = x + (size_t)p * rowsPerP * C;
    size_t total = (size_t)rowsPerP * C;
    size_t stride = (size_t)gridDim.x * blockDim.x;
    float ls = 0.0f, lq = 0.0f;
    for (size_t e = (size_t)blockIdx.x * blockDim.x + tid; e < total; e += stride) {
        float v = base[e];
        ls += v;
        lq = fmaf(v, v, lq);
    }
    int c = tid & (C - 1);
    atomicAdd(&ss[c], ls);
    atomicAdd(&sq[c], lq);
    __syncthreads();
    if (tid < C) {
        atomicAdd(&d_acc[slotOff + p * 2 * C + tid], ss[tid]);
        atomicAdd(&d_acc[slotOff + p * 2 * C + C + tid], sq[tid]);
    }
}

template <int C>
__global__ void k_bnapply(float* __restrict__ x, int rowsPerP, int slotOff,
                          const float* __restrict__ g, const float* __restrict__ b,
                          float invR) {
    __shared__ float sc[C], sh[C];
    int tid = threadIdx.x;
    if (tid < C) {
        float s = d_acc[slotOff + blockIdx.z * 2 * C + tid];
        float q = d_acc[slotOff + blockIdx.z * 2 * C + C + tid];
        float m = s * invR;
        float v = fmaf(-m, m, q * invR);
        if (v < 0.0f) v = 0.0f;
        float k = rsqrtf(v + 1e-5f) * g[tid];
        sc[tid] = k;
        sh[tid] = b[tid] - m * k;
    }
    __syncthreads();
    float* base = x + (size_t)blockIdx.z * rowsPerP * C;
    size_t total = (size_t)rowsPerP * C;
    size_t e = (size_t)blockIdx.x * blockDim.x + tid;
    if (e < total) {
        int c = tid & (C - 1);
        float y = fmaf(base[e], sc[c], sh[c]);
        base[e] = fmaxf(y, 0.0f);
    }
}

// ---------------------------------------------------------------------------
// Max-pool over K samples
// ---------------------------------------------------------------------------
__global__ void k_maxpool(const float* __restrict__ in, float* __restrict__ out,
                          int Stot, int K, int C) {
    int g = blockIdx.x * blockDim.x + threadIdx.x;
    if (g >= Stot * C) return;
    int s = g / C, c = g - s * C;
    const float* p = in + (size_t)s * K * C + c;
    float m = p[0];
    for (int k = 1; k < K; k++) m = fmaxf(m, p[(size_t)k * C]);
    out[g] = m;
}

// ---------------------------------------------------------------------------
// set_upconv layer1 matmul: in = [l2f[id] (64), l2x[id]-l1x[s] (3)]
// ---------------------------------------------------------------------------
__global__ void k_su1(const float* __restrict__ w) {
    __shared__ float sw[32 * 67];
    for (int i = threadIdx.x; i < 32 * 67; i += blockDim.x) sw[i] = w[i];
    __syncthreads();
    int g = blockIdx.x * blockDim.x + threadIdx.x;  // NI*S1*8 = 131072 exact
    int inst = g >> 15;
    int rem = g & 32767;
    int s = rem >> 3;
    int id = d_suidx[g];
    float in[67];
    const float* f = d_l2f + ((size_t)inst * S2 + id) * 64;
#pragma unroll
    for (int c = 0; c < 64; c++) in[c] = f[c];
    const float* p2 = d_l2x + ((size_t)inst * S2 + id) * 3;
    const float* p1 = d_l1x + ((size_t)inst * S1 + s) * 3;
    in[64] = p2[0] - p1[0]; in[65] = p2[1] - p1[1]; in[66] = p2[2] - p1[2];
    float* o = d_hsu + (size_t)g * 32;
    for (int oo = 0; oo < 32; oo++) {
        float acc = 0.0f;
#pragma unroll
        for (int c = 0; c < 67; c++) acc = fmaf(in[c], sw[oo * 67 + c], acc);
        o[oo] = acc;
    }
}

// Max over k=8 of hsu, concat with l1f -> hcat (64ch)
__global__ void k_su_cat() {
    int row = blockIdx.x * blockDim.x + threadIdx.x;  // NI*S1 = 16384 exact
    const float* h = d_hsu + (size_t)row * 8 * 32;
    float* o = d_hcat + (size_t)row * 64;
#pragma unroll 4
    for (int c = 0; c < 32; c++) {
        float m = h[c];
        for (int k = 1; k < 8; k++) m = fmaxf(m, h[k * 32 + c]);
        o[c] = m;
    }
    const float* f = d_l1f + (size_t)row * 32;
#pragma unroll 4
    for (int c = 0; c < 32; c++) o[32 + c] = f[c];
}

// ---------------------------------------------------------------------------
// Feature propagation: 3-NN interp of l1n + concat raw features -> fph (42ch)
// ---------------------------------------------------------------------------
__global__ void k_fp() {
    const int M = S1;  // 4096 ref points
    extern __shared__ float sm[];
    float* sx = sm; float* sy = sm + M; float* sz = sm + 2 * M; float* sp = sm + 3 * M;
    int inst = blockIdx.y;
    const float* ref = d_l1x + inst * M * 3;
    for (int j = threadIdx.x; j < M; j += blockDim.x) {
        float x = ref[3 * j], y = ref[3 * j + 1], z = ref[3 * j + 2];
        sx[j] = x; sy[j] = y; sz[j] = z;
        sp[j] = sumsq3(x, y, z);
    }
    __syncthreads();
    int q = blockIdx.x * blockDim.x + threadIdx.x;  // S=8192
    const float* qp = d_pts + ((size_t)inst * N0 + q) * 3;
    float qx = qp[0], qy = qp[1], qz = qp[2];
    float qq = sumsq3(qx, qy, qz);
    float bd[3]; int bi[3];
#pragma unroll
    for (int k = 0; k < 3; k++) { bd[k] = 3.402823466e38f; bi[k] = 0x7fffffff; }
    for (int j = 0; j < M; j++) {
        float d = expdist(qx, qy, qz, qq, sx[j], sy[j], sz[j], sp[j]);
        topk_insert<3>(d, j, bd, bi);
    }
    float w0 = 1.0f / fmaxf(bd[0], 1e-10f);
    float w1 = 1.0f / fmaxf(bd[1], 1e-10f);
    float w2 = 1.0f / fmaxf(bd[2], 1e-10f);
    float s = (w0 + w1) + w2;
    w0 /= s; w1 /= s; w2 /= s;
    const float* f0 = d_l1n + ((size_t)inst * S1 + bi[0]) * 32;
    const float* f1 = d_l1n + ((size_t)inst * S1 + bi[1]) * 32;
    const float* f2 = d_l1n + ((size_t)inst * S1 + bi[2]) * 32;
    float* o = d_fph + ((size_t)inst * N0 + q) * 42;
#pragma unroll 4
    for (int c = 0; c < 32; c++)
        o[c] = f0[c] * w0 + f1[c] * w1 + f2[c] * w2;
    const float* fr = d_fea + ((size_t)inst * N0 + q) * C0;
#pragma unroll
    for (int c = 0; c < C0; c++) o[32 + c] = fr[c];
}

// ---------------------------------------------------------------------------
// Final: sf = x @ conv2_w^T + b; out = concat(pts, sf)  -> (2, B, N, 19)
// ---------------------------------------------------------------------------
__global__ void k_final(const float* __restrict__ w, const float* __restrict__ b,
                        float* __restrict__ out) {
    __shared__ float sw[16 * 32];
    for (int i = threadIdx.x; i < 16 * 32; i += blockDim.x) sw[i] = w[i];
    __syncthreads();
    int g = blockIdx.x * blockDim.x + threadIdx.x;  // NI*N0 = 32768 exact
    float in[32];
    const float* src = d_l0n + (size_t)g * 32;
#pragma unroll
    for (int c = 0; c < 32; c++) in[c] = src[c];
    float* o = out + (size_t)g * 19;
    const float* p = d_pts + (size_t)g * 3;
    o[0] = p[0]; o[1] = p[1]; o[2] = p[2];
    for (int oo = 0; oo < 16; oo++) {
        float acc = 0.0f;
#pragma unroll
        for (int c = 0; c < 32; c++) acc = fmaf(in[c], sw[oo * 32 + c], acc);
        o[3 + oo] = acc + b[oo];
    }
}

// ---------------------------------------------------------------------------
// Host
// ---------------------------------------------------------------------------
template <int C>
static void run_bn(float* buf, int rowsPerP, int slot, const float* g, const float* b) {
    size_t total = (size_t)rowsPerP * C;
    dim3 rg(64, 1, P_);
    k_bnreduce<C><<<rg, 256>>>(buf, rowsPerP, slot);
    dim3 ag((unsigned)((total + 255) / 256), 1, P_);
    k_bnapply<C><<<ag, 256>>>(buf, rowsPerP, slot, g, b, 1.0f / (float)total * (float)C);
}

extern "C" void kernel_launch(void* const* d_in, const int* in_sizes, int n_in,
                              void* d_out, int out_size) {
    const float* points1 = (const float*)d_in[0];
    const float* fea1    = (const float*)d_in[1];
    const float* points2 = (const float*)d_in[2];
    const float* fea2    = (const float*)d_in[3];
    const float* sa1_w0  = (const float*)d_in[4];
    const float* sa1_g0  = (const float*)d_in[5];
    const float* sa1_b0  = (const float*)d_in[6];
    const float* sa1_w1  = (const float*)d_in[7];
    const float* sa1_g1  = (const float*)d_in[8];
    const float* sa1_b1  = (const float*)d_in[9];
    const float* sa2_w0  = (const float*)d_in[10];
    const float* sa2_g0  = (const float*)d_in[11];
    const float* sa2_b0  = (const float*)d_in[12];
    const float* sa2_w1  = (const float*)d_in[13];
    const float* sa2_g1  = (const float*)d_in[14];
    const float* sa2_b1  = (const float*)d_in[15];
    const float* su1_w1  = (const float*)d_in[16];
    const float* su1_g1  = (const float*)d_in[17];
    const float* su1_b1  = (const float*)d_in[18];
    const float* su1_w2  = (const float*)d_in[19];
    const float* su1_g2  = (const float*)d_in[20];
    const float* su1_b2  = (const float*)d_in[21];
    const float* fp_w    = (const float*)d_in[22];
    const float* fp_g    = (const float*)d_in[23];
    const float* fp_b    = (const float*)d_in[24];
    const float* bn1_g   = (const float*)d_in[25];
    const float* bn1_b   = (const float*)d_in[26];
    const float* conv2_w = (const float*)d_in[27];
    const float* conv2_b = (const float*)d_in[28];

    float *g_pts, *g_fea, *g_l1x, *g_l2x, *g_h1a, *g_h1b, *g_l1f, *g_h2a, *g_h2b,
          *g_l2f, *g_hsu, *g_hcat, *g_l1n, *g_fph, *g_l0n;
    int *g_fps1, *g_fps2, *g_gidx1, *g_gidx2, *g_suidx;
    cudaGetSymbolAddress((void**)&g_pts,  d_pts);
    cudaGetSymbolAddress((void**)&g_fea,  d_fea);
    cudaGetSymbolAddress((void**)&g_l1x,  d_l1x);
    cudaGetSymbolAddress((void**)&g_l2x,  d_l2x);
    cudaGetSymbolAddress((void**)&g_h1a,  d_h1a);
    cudaGetSymbolAddress((void**)&g_h1b,  d_h1b);
    cudaGetSymbolAddress((void**)&g_l1f,  d_l1f);
    cudaGetSymbolAddress((void**)&g_h2a,  d_h2a);
    cudaGetSymbolAddress((void**)&g_h2b,  d_h2b);
    cudaGetSymbolAddress((void**)&g_l2f,  d_l2f);
    cudaGetSymbolAddress((void**)&g_hsu,  d_hsu);
    cudaGetSymbolAddress((void**)&g_hcat, d_hcat);
    cudaGetSymbolAddress((void**)&g_l1n,  d_l1n);
    cudaGetSymbolAddress((void**)&g_fph,  d_fph);
    cudaGetSymbolAddress((void**)&g_l0n,  d_l0n);
    cudaGetSymbolAddress((void**)&g_fps1, d_fps1);
    cudaGetSymbolAddress((void**)&g_fps2, d_fps2);
    cudaGetSymbolAddress((void**)&g_gidx1, d_gidx1);
    cudaGetSymbolAddress((void**)&g_gidx2, d_gidx2);
    cudaGetSymbolAddress((void**)&g_suidx, d_suidx);

    cudaFuncSetAttribute(k_fps<8>,    cudaFuncAttributeMaxDynamicSharedMemorySize, 98304);
    cudaFuncSetAttribute(k_fps<4>,    cudaFuncAttributeMaxDynamicSharedMemorySize, 65536);
    cudaFuncSetAttribute(k_ballquery, cudaFuncAttributeMaxDynamicSharedMemorySize, 131072);
    cudaFuncSetAttribute(k_fp,        cudaFuncAttributeMaxDynamicSharedMemorySize, 65536);

    k_init<<<1280, 256>>>(points1, fea1, points2, fea2);

    // --- SA1 ---
    k_fps<8><<<NI, 1024, 98304>>>(g_pts, N0, S1, g_fps1, g_l1x);
    k_ballquery<<<dim3(S1 / 256, NI), 256, 131072>>>(g_pts, g_l1x, N0, S1,
                                                     (float)(0.1 * 0.1), g_gidx1);
    k_group_mm<10, 16><<<1024, 256>>>(g_pts, g_l1x, g_fea, g_gidx1, sa1_w0, g_h1a,
                                      N0, S1, NI * S1 * 16);
    run_bn<16>(g_h1a, B_ * S1 * 16, SL_SA1A, sa1_g0, sa1_b0);
    k_dense<16, 32><<<1024, 256>>>(g_h1a, sa1_w1, g_h1b, NI * S1 * 16);
    run_bn<32>(g_h1b, B_ * S1 * 16, SL_SA1B, sa1_g1, sa1_b1);
    k_maxpool<<<2048, 256>>>(g_h1b, g_l1f, NI * S1, 16, 32);

    // --- SA2 ---
    k_fps<4><<<NI, 1024, 49152>>>(g_l1x, S1, S2, g_fps2, g_l2x);
    k_ballquery<<<dim3(S2 / 256, NI), 256, 65536>>>(g_l1x, g_l2x, S1, S2,
                                                    (float)(0.2 * 0.2), g_gidx2);
    k_group_mm<32, 32><<<256, 256>>>(g_l1x, g_l2x, g_l1f, g_gidx2, sa2_w0, g_h2a,
                                     S1, S2, NI * S2 * 16);
    run_bn<32>(g_h2a, B_ * S2 * 16, SL_SA2A, sa2_g0, sa2_b0);
    k_dense<32, 64><<<256, 256>>>(g_h2a, sa2_w1, g_h2b, NI * S2 * 16);
    run_bn<64>(g_h2b, B_ * S2 * 16, SL_SA2B, sa2_g1, sa2_b1);
    k_maxpool<<<1024, 256>>>(g_h2b, g_l2f, NI * S2, 16, 64);

    // --- set_upconv ---
    k_knn<8><<<dim3(S1 / 256, NI), 256, 4 * S2 * 4>>>(g_l2x, g_l1x, S2, S1, g_suidx);
    k_su1<<<512, 256>>>(su1_w1);
    run_bn<32>(g_hsu, B_ * S1 * 8, SL_SU1, su1_g1, su1_b1);
    k_su_cat<<<64, 256>>>();
    k_dense<64, 32><<<64, 256>>>(g_hcat, su1_w2, g_l1n, NI * S1);
    run_bn<32>(g_l1n, B_ * S1, SL_SU2, su1_g2, su1_b2);

    // --- feature propagation ---
    k_fp<<<dim3(N0 / 256, NI), 256, 65536>>>();
    k_dense<42, 32><<<128, 256>>>(g_fph, fp_w, g_l0n, NI * N0);
    run_bn<32>(g_l0n, B_ * N0, SL_FP, fp_g, fp_b);
    run_bn<32>(g_l0n, B_ * N0, SL_BN1, bn1_g, bn1_b);

    // --- final conv + concat ---
    k_final<<<128, 256>>>(conv2_w, conv2_b, (float*)d_out);
}

// round 9
// speedup vs baseline: 1.0001x; 1.0001x over previous
#include <cuda_runtime.h>

// ---------------------------------------------------------------------------
// Problem constants
// ---------------------------------------------------------------------------
constexpr int P_ = 2;           // two pipelines (points1/points2)
constexpr int B_ = 2;           // batch per pipeline
constexpr int NI = P_ * B_;     // 4 independent instances
constexpr int N0 = 8192;        // input points
constexpr int C0 = 10;          // input feature channels
constexpr int S1 = 4096;        // SA1 npoint
constexpr int S2 = 1024;        // SA2 npoint

// ---------------------------------------------------------------------------
// Scratch (static device globals — no allocation allowed)
// ---------------------------------------------------------------------------
__device__ float d_pts [NI * N0 * 3];
__device__ float d_fea [NI * N0 * C0];
__device__ int   d_fps1[NI * S1];
__device__ float d_l1x [NI * S1 * 3];
__device__ int   d_gidx1[NI * S1 * 16];
__device__ float d_h1a [NI * S1 * 16 * 16];
__device__ float d_h1b [NI * S1 * 16 * 32];
__device__ float d_l1f [NI * S1 * 32];
__device__ int   d_fps2[NI * S2];
__device__ float d_l2x [NI * S2 * 3];
__device__ int   d_gidx2[NI * S2 * 16];
__device__ float d_h2a [NI * S2 * 16 * 32];
__device__ float d_h2b [NI * S2 * 16 * 64];
__device__ float d_l2f [NI * S2 * 64];
__device__ int   d_suidx[NI * S1 * 8];
__device__ float d_hsu [NI * S1 * 8 * 32];
__device__ float d_hcat[NI * S1 * 64];
__device__ float d_l1n [NI * S1 * 32];
__device__ float d_fph [NI * N0 * 42];
__device__ float d_l0n [NI * N0 * 32];
__device__ float d_acc [1088];   // BN accumulators for all 8 BN sites

// BN accumulator slot offsets (each slot holds P_*2*C floats)
constexpr int SL_SA1A = 0;     // C=16
constexpr int SL_SA1B = 64;    // C=32
constexpr int SL_SA2A = 192;   // C=32
constexpr int SL_SA2B = 320;   // C=64
constexpr int SL_SU1  = 576;   // C=32
constexpr int SL_SU2  = 704;   // C=32
constexpr int SL_FP   = 832;   // C=32
constexpr int SL_BN1  = 960;   // C=32

// ---------------------------------------------------------------------------
// Helpers
// ---------------------------------------------------------------------------
__device__ __forceinline__ float sumsq3(float x, float y, float z) {
    // strict mul/add — matches XLA elementwise+reduce fusion (no fma)
    return __fadd_rn(__fadd_rn(__fmul_rn(x, x), __fmul_rn(y, y)), __fmul_rn(z, z));
}
__device__ __forceinline__ float expdist(float qx, float qy, float qz, float qq,
                                         float px, float py, float pz, float pp) {
    // dot product via fma chain — matches Eigen dot_general K-loop (fma accumulate)
    float dot = fmaf(qz, pz, fmaf(qy, py, __fmul_rn(qx, px)));
    return __fsub_rn(__fadd_rn(qq, pp), __fmul_rn(2.0f, dot));
}
template <int KK>
__device__ __forceinline__ void topk_insert(float d, int j, float* bd, int* bi) {
    if (d < bd[KK - 1] || (d == bd[KK - 1] && j < bi[KK - 1])) {
        bd[KK - 1] = d; bi[KK - 1] = j;
#pragma unroll
        for (int t = KK - 1; t > 0; t--) {
            if (bd[t] < bd[t - 1] || (bd[t] == bd[t - 1] && bi[t] < bi[t - 1])) {
                float td = bd[t]; bd[t] = bd[t - 1]; bd[t - 1] = td;
                int   ti = bi[t]; bi[t] = bi[t - 1]; bi[t - 1] = ti;
            }
        }
    }
}

// ---------------------------------------------------------------------------
// Init: pack inputs into per-instance buffers, zero BN accumulators
// ---------------------------------------------------------------------------
__global__ void k_init(const float* __restrict__ p1, const float* __restrict__ f1,
                       const float* __restrict__ p2, const float* __restrict__ f2) {
    int i = blockIdx.x * blockDim.x + threadIdx.x;
    if (i < NI * N0 * 3)
        d_pts[i] = (i < B_ * N0 * 3) ? p1[i] : p2[i - B_ * N0 * 3];
    if (i < NI * N0 * C0)
        d_fea[i] = (i < B_ * N0 * C0) ? f1[i] : f2[i - B_ * N0 * C0];
    if (i < 1088) d_acc[i] = 0.0f;
}

// ---------------------------------------------------------------------------
// Farthest point sampling: one 1024-thread block per instance.
// ---------------------------------------------------------------------------
template <int NPT>
__global__ void __launch_bounds__(1024) k_fps(const float* __restrict__ ptsAll,
                                              int N, int npoint,
                                              int* __restrict__ idxAll,
                                              float* __restrict__ nxyzAll) {
    const int T = 1024;
    int inst = blockIdx.x;
    const float* xyz = ptsAll + inst * N * 3;
    int*   idx_out = idxAll + inst * npoint;
    float* nxyz    = nxyzAll + inst * npoint * 3;

    extern __shared__ float sm[];
    float* sx = sm; float* sy = sm + N; float* sz = sm + 2 * N;
    __shared__ float s_rv[32];
    __shared__ int   s_ri[32];
    __shared__ float s_c[3];

    int tid = threadIdx.x;
    int lane = tid & 31, wid = tid >> 5;

    float px[NPT], py[NPT], pz[NPT], dd[NPT];
#pragma unroll
    for (int u = 0; u < NPT; u++) {
        int j = tid + u * T;
        px[u] = xyz[3 * j]; py[u] = xyz[3 * j + 1]; pz[u] = xyz[3 * j + 2];
        dd[u] = 1e10f;
        sx[j] = px[u]; sy[j] = py[u]; sz[j] = pz[u];
    }
    if (tid == 0) {
        idx_out[0] = 0;
        s_c[0] = xyz[0]; s_c[1] = xyz[1]; s_c[2] = xyz[2];
    }

    for (int i = 0; i < npoint - 1; i++) {
        __syncthreads();
        float cx = s_c[0], cy = s_c[1], cz = s_c[2];
        float bv = -1.0f; int bi = 0;
#pragma unroll
        for (int u = 0; u < NPT; u++) {
            float dx = __fsub_rn(px[u], cx);
            float dy = __fsub_rn(py[u], cy);
            float dz = __fsub_rn(pz[u], cz);
            float d = sumsq3(dx, dy, dz);
            float nd = fminf(dd[u], d);
            dd[u] = nd;
            if (nd > bv) { bv = nd; bi = tid + u * T; }
        }
#pragma unroll
        for (int off = 16; off > 0; off >>= 1) {
            float ov = __shfl_down_sync(0xffffffffu, bv, off);
            int   oi = __shfl_down_sync(0xffffffffu, bi, off);
            if (ov > bv || (ov == bv && oi < bi)) { bv = ov; bi = oi; }
        }
        if (lane == 0) { s_rv[wid] = bv; s_ri[wid] = bi; }
        __syncthreads();
        if (wid == 0) {
            bv = s_rv[lane]; bi = s_ri[lane];
#pragma unroll
            for (int off = 16; off > 0; off >>= 1) {
                float ov = __shfl_down_sync(0xffffffffu, bv, off);
                int   oi = __shfl_down_sync(0xffffffffu, bi, off);
                if (ov > bv || (ov == bv && oi < bi)) { bv = ov; bi = oi; }
            }
            if (lane == 0) {
                idx_out[i + 1] = bi;
                s_c[0] = sx[bi]; s_c[1] = sy[bi]; s_c[2] = sz[bi];
            }
        }
    }
    __syncthreads();
    for (int s = tid; s < npoint; s += T) {
        int id = idx_out[s];
        nxyz[3 * s] = sx[id]; nxyz[3 * s + 1] = sy[id]; nxyz[3 * s + 2] = sz[id];
    }
}

// ---------------------------------------------------------------------------
// Ball query: first 16 in-range indices (== 16 smallest) + nearest fallback
// ---------------------------------------------------------------------------
__global__ void k_ballquery(const float* __restrict__ ptsAll, const float* __restrict__ qAll,
                            int N, int S, float r2, int* __restrict__ gidxAll) {
    extern __shared__ float sm[];
    float* sx = sm; float* sy = sm + N; float* sz = sm + 2 * N; float* sp = sm + 3 * N;
    int inst = blockIdx.y;
    const float* pts = ptsAll + inst * N * 3;
    for (int j = threadIdx.x; j < N; j += blockDim.x) {
        float x = pts[3 * j], y = pts[3 * j + 1], z = pts[3 * j + 2];
        sx[j] = x; sy[j] = y; sz[j] = z;
        sp[j] = sumsq3(x, y, z);
    }
    __syncthreads();
    int q = blockIdx.x * blockDim.x + threadIdx.x;
    if (q >= S) return;
    const float* nq = qAll + (inst * S + q) * 3;
    float qx = nq[0], qy = nq[1], qz = nq[2];
    float qq = sumsq3(qx, qy, qz);

    int res[16]; int cnt = 0;
    float dmin = 3.402823466e38f; int jmin = 0;
    for (int j = 0; j < N; j++) {
        float d = expdist(qx, qy, qz, qq, sx[j], sy[j], sz[j], sp[j]);
        if (d < dmin) { dmin = d; jmin = j; }
        if (d <= r2) { res[cnt++] = j; if (cnt == 16) break; }
    }
    int* out = gidxAll + (inst * S + q) * 16;
    if (cnt == 0) {
        for (int k = 0; k < 16; k++) out[k] = jmin;
    } else {
        int f = res[0];
        for (int k = 0; k < 16; k++) out[k] = (k < cnt) ? res[k] : f;
    }
}

// ---------------------------------------------------------------------------
// kNN (k smallest distances, stable tie-break) — set_upconv (k=8)
// ---------------------------------------------------------------------------
template <int KK>
__global__ void k_knn(const float* __restrict__ refAll, const float* __restrict__ qAll,
                      int M, int S, int* __restrict__ outIdx) {
    extern __shared__ float sm[];
    float* sx = sm; float* sy = sm + M; float* sz = sm + 2 * M; float* sp = sm + 3 * M;
    int inst = blockIdx.y;
    const float* ref = refAll + inst * M * 3;
    for (int j = threadIdx.x; j < M; j += blockDim.x) {
        float x = ref[3 * j], y = ref[3 * j + 1], z = ref[3 * j + 2];
        sx[j] = x; sy[j] = y; sz[j] = z;
        sp[j] = sumsq3(x, y, z);
    }
    __syncthreads();
    int q = blockIdx.x * blockDim.x + threadIdx.x;
    if (q >= S) return;
    const float* qp = qAll + (inst * S + q) * 3;
    float qx = qp[0], qy = qp[1], qz = qp[2];
    float qq = sumsq3(qx, qy, qz);
    float bd[KK]; int bi[KK];
#pragma unroll
    for (int k = 0; k < KK; k++) { bd[k] = 3.402823466e38f; bi[k] = 0x7fffffff; }
    for (int j = 0; j < M; j++) {
        float d = expdist(qx, qy, qz, qq, sx[j], sy[j], sz[j], sp[j]);
        topk_insert<KK>(d, j, bd, bi);
    }
    int* o = outIdx + (inst * S + q) * KK;
#pragma unroll
    for (int k = 0; k < KK; k++) o[k] = bi[k];
}

// ---------------------------------------------------------------------------
// SA layer0 matmul with fused grouping: in = [xyz[id]-newxyz, feat[id]]
// ---------------------------------------------------------------------------
template <int CF, int O>
__global__ void k_group_mm(const float* __restrict__ ptsAll, const float* __restrict__ nxyzAll,
                           const float* __restrict__ featAll, const int* __restrict__ gidxAll,
                           const float* __restrict__ w, float* __restrict__ outAll,
                           int N, int S, int rowsTotal) {
    const int CIN = CF + 3;
    __shared__ float sw[O * CIN];
    for (int i = threadIdx.x; i < O * CIN; i += blockDim.x) sw[i] = w[i];
    __syncthreads();
    int g = blockIdx.x * blockDim.x + threadIdx.x;
    if (g >= rowsTotal) return;
    int sk = S * 16;
    int inst = g / sk;
    int rem = g - inst * sk;
    int s = rem >> 4;
    int id = gidxAll[g];
    const float* p = ptsAll + (inst * N + id) * 3;
    const float* nx = nxyzAll + (inst * S + s) * 3;
    float in[CIN];
    in[0] = p[0] - nx[0]; in[1] = p[1] - nx[1]; in[2] = p[2] - nx[2];
    const float* f = featAll + (inst * N + id) * CF;
#pragma unroll
    for (int c = 0; c < CF; c++) in[3 + c] = f[c];
    float* o = outAll + (size_t)g * O;
    for (int oo = 0; oo < O; oo++) {
        float acc = 0.0f;
#pragma unroll
        for (int c = 0; c < CIN; c++) acc = fmaf(in[c], sw[oo * CIN + c], acc);
        o[oo] = acc;
    }
}

// ---------------------------------------------------------------------------
// Dense row matmul
// ---------------------------------------------------------------------------
template <int CIN, int O>
__global__ void k_dense(const float* __restrict__ inAll, const float* __restrict__ w,
                        float* __restrict__ outAll, int rows) {
    __shared__ float sw[O * CIN];
    for (int i = threadIdx.x; i < O * CIN; i += blockDim.x) sw[i] = w[i];
    __syncthreads();
    int g = blockIdx.x * blockDim.x + threadIdx.x;
    if (g >= rows) return;
    float in[CIN];
    const float* src = inAll + (size_t)g * CIN;
#pragma unroll
    for (int c = 0; c < CIN; c++) in[c] = src[c];
    float* o = outAll + (size_t)g * O;
    for (int oo = 0; oo < O; oo++) {
        float acc = 0.0f;
#pragma unroll
        for (int c = 0; c < CIN; c++) acc = fmaf(in[c], sw[oo * CIN + c], acc);
        o[oo] = acc;
    }
}

// ---------------------------------------------------------------------------
// BN reduce (sum, sumsq per channel per pipeline) + apply scale/shift + relu
// ---------------------------------------------------------------------------
template <int C>
__global__ void k_bnreduce(const float* __restrict__ x, int rowsPerP, int slotOff) {
    __shared__ float ss[C], sq[C];
    int tid = threadIdx.x;
    if (tid < C) { ss[tid] = 0.0f; sq[tid] = 0.0f; }
    __syncthreads();
    int p = blockIdx.z;
    const float* base = x + (size_t)p * rowsPerP * C;
    size_t total = (size_t)rowsPerP * C;
    size_t stride = (size_t)gridDim.x * blockDim.x;
    float ls = 0.0f, lq = 0.0f;
    for (size_t e = (size_t)blockIdx.x * blockDim.x + tid; e < total; e += stride) {
        float v = base[e];
        ls += v;
        lq = fmaf(v, v, lq);
    }
    int c = tid & (C - 1);
    atomicAdd(&ss[c], ls);
    atomicAdd(&sq[c], lq);
    __syncthreads();
    if (tid < C) {
        atomicAdd(&d_acc[slotOff + p * 2 * C + tid], ss[tid]);
        atomicAdd(&d_acc[slotOff + p * 2 * C + C + tid], sq[tid]);
    }
}

template <int C>
__global__ void k_bnapply(float* __restrict__ x, int rowsPerP, int slotOff,
                          const float* __restrict__ g, const float* __restrict__ b,
                          float invR) {
    __shared__ float sc[C], sh[C];
    int tid = threadIdx.x;
    if (tid < C) {
        float s = d_acc[slotOff + blockIdx.z * 2 * C + tid];
        float q = d_acc[slotOff + blockIdx.z * 2 * C + C + tid];
        float m = s * invR;
        float v = fmaf(-m, m, q * invR);
        if (v < 0.0f) v = 0.0f;
        float k = rsqrtf(v + 1e-5f) * g[tid];
        sc[tid] = k;
        sh[tid] = b[tid] - m * k;
    }
    __syncthreads();
    float* base = x + (size_t)blockIdx.z * rowsPerP * C;
    size_t total = (size_t)rowsPerP * C;
    size_t e = (size_t)blockIdx.x * blockDim.x + tid;
    if (e < total) {
        int c = tid & (C - 1);
        float y = fmaf(base[e], sc[c], sh[c]);
        base[e] = fmaxf(y, 0.0f);
    }
}

// ---------------------------------------------------------------------------
// Max-pool over K samples
// ---------------------------------------------------------------------------
__global__ void k_maxpool(const float* __restrict__ in, float* __restrict__ out,
                          int Stot, int K, int C) {
    int g = blockIdx.x * blockDim.x + threadIdx.x;
    if (g >= Stot * C) return;
    int s = g / C, c = g - s * C;
    const float* p = in + (size_t)s * K * C + c;
    float m = p[0];
    for (int k = 1; k < K; k++) m = fmaxf(m, p[(size_t)k * C]);
    out[g] = m;
}

// ---------------------------------------------------------------------------
// set_upconv layer1 matmul: in = [l2f[id] (64), l2x[id]-l1x[s] (3)]
// ---------------------------------------------------------------------------
__global__ void k_su1(const float* __restrict__ w) {
    __shared__ float sw[32 * 67];
    for (int i = threadIdx.x; i < 32 * 67; i += blockDim.x) sw[i] = w[i];
    __syncthreads();
    int g = blockIdx.x * blockDim.x + threadIdx.x;  // NI*S1*8 = 131072 exact
    int inst = g >> 15;
    int rem = g & 32767;
    int s = rem >> 3;
    int id = d_suidx[g];
    float in[67];
    const float* f = d_l2f + ((size_t)inst * S2 + id) * 64;
#pragma unroll
    for (int c = 0; c < 64; c++) in[c] = f[c];
    const float* p2 = d_l2x + ((size_t)inst * S2 + id) * 3;
    const float* p1 = d_l1x + ((size_t)inst * S1 + s) * 3;
    in[64] = p2[0] - p1[0]; in[65] = p2[1] - p1[1]; in[66] = p2[2] - p1[2];
    float* o = d_hsu + (size_t)g * 32;
    for (int oo = 0; oo < 32; oo++) {
        float acc = 0.0f;
#pragma unroll
        for (int c = 0; c < 67; c++) acc = fmaf(in[c], sw[oo * 67 + c], acc);
        o[oo] = acc;
    }
}

// Max over k=8 of hsu, concat with l1f -> hcat (64ch)
__global__ void k_su_cat() {
    int row = blockIdx.x * blockDim.x + threadIdx.x;  // NI*S1 = 16384 exact
    const float* h = d_hsu + (size_t)row * 8 * 32;
    float* o = d_hcat + (size_t)row * 64;
#pragma unroll 4
    for (int c = 0; c < 32; c++) {
        float m = h[c];
        for (int k = 1; k < 8; k++) m = fmaxf(m, h[k * 32 + c]);
        o[c] = m;
    }
    const float* f = d_l1f + (size_t)row * 32;
#pragma unroll 4
    for (int c = 0; c < 32; c++) o[32 + c] = f[c];
}

// ---------------------------------------------------------------------------
// Feature propagation: 3-NN interp of l1n + concat raw features -> fph (42ch)
// ---------------------------------------------------------------------------
__global__ void k_fp() {
    const int M = S1;  // 4096 ref points
    extern __shared__ float sm[];
    float* sx = sm; float* sy = sm + M; float* sz = sm + 2 * M; float* sp = sm + 3 * M;
    int inst = blockIdx.y;
    const float* ref = d_l1x + inst * M * 3;
    for (int j = threadIdx.x; j < M; j += blockDim.x) {
        float x = ref[3 * j], y = ref[3 * j + 1], z = ref[3 * j + 2];
        sx[j] = x; sy[j] = y; sz[j] = z;
        sp[j] = sumsq3(x, y, z);
    }
    __syncthreads();
    int q = blockIdx.x * blockDim.x + threadIdx.x;  // S=8192
    const float* qp = d_pts + ((size_t)inst * N0 + q) * 3;
    float qx = qp[0], qy = qp[1], qz = qp[2];
    float qq = sumsq3(qx, qy, qz);
    float bd[3]; int bi[3];
#pragma unroll
    for (int k = 0; k < 3; k++) { bd[k] = 3.402823466e38f; bi[k] = 0x7fffffff; }
    for (int j = 0; j < M; j++) {
        float d = expdist(qx, qy, qz, qq, sx[j], sy[j], sz[j], sp[j]);
        topk_insert<3>(d, j, bd, bi);
    }
    float w0 = 1.0f / fmaxf(bd[0], 1e-10f);
    float w1 = 1.0f / fmaxf(bd[1], 1e-10f);
    float w2 = 1.0f / fmaxf(bd[2], 1e-10f);
    float s = (w0 + w1) + w2;
    w0 /= s; w1 /= s; w2 /= s;
    const float* f0 = d_l1n + ((size_t)inst * S1 + bi[0]) * 32;
    const float* f1 = d_l1n + ((size_t)inst * S1 + bi[1]) * 32;
    const float* f2 = d_l1n + ((size_t)inst * S1 + bi[2]) * 32;
    float* o = d_fph + ((size_t)inst * N0 + q) * 42;
#pragma unroll 4
    for (int c = 0; c < 32; c++)
        o[c] = f0[c] * w0 + f1[c] * w1 + f2[c] * w2;
    const float* fr = d_fea + ((size_t)inst * N0 + q) * C0;
#pragma unroll
    for (int c = 0; c < C0; c++) o[32 + c] = fr[c];
}

// ---------------------------------------------------------------------------
// Final: sf = x @ conv2_w^T + b; out = concat(pts, sf)  -> (2, B, N, 19)
// ---------------------------------------------------------------------------
__global__ void k_final(const float* __restrict__ w, const float* __restrict__ b,
                        float* __restrict__ out) {
    __shared__ float sw[16 * 32];
    for (int i = threadIdx.x; i < 16 * 32; i += blockDim.x) sw[i] = w[i];
    __syncthreads();
    int g = blockIdx.x * blockDim.x + threadIdx.x;  // NI*N0 = 32768 exact
    float in[32];
    const float* src = d_l0n + (size_t)g * 32;
#pragma unroll
    for (int c = 0; c < 32; c++) in[c] = src[c];
    float* o = out + (size_t)g * 19;
    const float* p = d_pts + (size_t)g * 3;
    o[0] = p[0]; o[1] = p[1]; o[2] = p[2];
    for (int oo = 0; oo < 16; oo++) {
        float acc = 0.0f;
#pragma unroll
        for (int c = 0; c < 32; c++) acc = fmaf(in[c], sw[oo * 32 + c], acc);
        o[3 + oo] = acc + b[oo];
    }
}

// ---------------------------------------------------------------------------
// Host
// ---------------------------------------------------------------------------
template <int C>
static void run_bn(float* buf, int rowsPerP, int slot, const float* g, const float* b) {
    size_t total = (size_t)rowsPerP * C;
    dim3 rg(64, 1, P_);
    k_bnreduce<C><<<rg, 256>>>(buf, rowsPerP, slot);
    dim3 ag((unsigned)((total + 255) / 256), 1, P_);
    k_bnapply<C><<<ag, 256>>>(buf, rowsPerP, slot, g, b, 1.0f / (float)total * (float)C);
}

extern "C" void kernel_launch(void* const* d_in, const int* in_sizes, int n_in,
                              void* d_out, int out_size) {
    const float* points1 = (const float*)d_in[0];
    const float* fea1    = (const float*)d_in[1];
    const float* points2 = (const float*)d_in[2];
    const float* fea2    = (const float*)d_in[3];
    const float* sa1_w0  = (const float*)d_in[4];
    const float* sa1_g0  = (const float*)d_in[5];
    const float* sa1_b0  = (const float*)d_in[6];
    const float* sa1_w1  = (const float*)d_in[7];
    const float* sa1_g1  = (const float*)d_in[8];
    const float* sa1_b1  = (const float*)d_in[9];
    const float* sa2_w0  = (const float*)d_in[10];
    const float* sa2_g0  = (const float*)d_in[11];
    const float* sa2_b0  = (const float*)d_in[12];
    const float* sa2_w1  = (const float*)d_in[13];
    const float* sa2_g1  = (const float*)d_in[14];
    const float* sa2_b1  = (const float*)d_in[15];
    const float* su1_w1  = (const float*)d_in[16];
    const float* su1_g1  = (const float*)d_in[17];
    const float* su1_b1  = (const float*)d_in[18];
    const float* su1_w2  = (const float*)d_in[19];
    const float* su1_g2  = (const float*)d_in[20];
    const float* su1_b2  = (const float*)d_in[21];
    const float* fp_w    = (const float*)d_in[22];
    const float* fp_g    = (const float*)d_in[23];
    const float* fp_b    = (const float*)d_in[24];
    const float* bn1_g   = (const float*)d_in[25];
    const float* bn1_b   = (const float*)d_in[26];
    const float* conv2_w = (const float*)d_in[27];
    const float* conv2_b = (const float*)d_in[28];

    float *g_pts, *g_fea, *g_l1x, *g_l2x, *g_h1a, *g_h1b, *g_l1f, *g_h2a, *g_h2b,
          *g_l2f, *g_hsu, *g_hcat, *g_l1n, *g_fph, *g_l0n;
    int *g_fps1, *g_fps2, *g_gidx1, *g_gidx2, *g_suidx;
    cudaGetSymbolAddress((void**)&g_pts,  d_pts);
    cudaGetSymbolAddress((void**)&g_fea,  d_fea);
    cudaGetSymbolAddress((void**)&g_l1x,  d_l1x);
    cudaGetSymbolAddress((void**)&g_l2x,  d_l2x);
    cudaGetSymbolAddress((void**)&g_h1a,  d_h1a);
    cudaGetSymbolAddress((void**)&g_h1b,  d_h1b);
    cudaGetSymbolAddress((void**)&g_l1f,  d_l1f);
    cudaGetSymbolAddress((void**)&g_h2a,  d_h2a);
    cudaGetSymbolAddress((void**)&g_h2b,  d_h2b);
    cudaGetSymbolAddress((void**)&g_l2f,  d_l2f);
    cudaGetSymbolAddress((void**)&g_hsu,  d_hsu);
    cudaGetSymbolAddress((void**)&g_hcat, d_hcat);
    cudaGetSymbolAddress((void**)&g_l1n,  d_l1n);
    cudaGetSymbolAddress((void**)&g_fph,  d_fph);
    cudaGetSymbolAddress((void**)&g_l0n,  d_l0n);
    cudaGetSymbolAddress((void**)&g_fps1, d_fps1);
    cudaGetSymbolAddress((void**)&g_fps2, d_fps2);
    cudaGetSymbolAddress((void**)&g_gidx1, d_gidx1);
    cudaGetSymbolAddress((void**)&g_gidx2, d_gidx2);
    cudaGetSymbolAddress((void**)&g_suidx, d_suidx);

    cudaFuncSetAttribute(k_fps<8>,    cudaFuncAttributeMaxDynamicSharedMemorySize, 98304);
    cudaFuncSetAttribute(k_fps<4>,    cudaFuncAttributeMaxDynamicSharedMemorySize, 65536);
    cudaFuncSetAttribute(k_ballquery, cudaFuncAttributeMaxDynamicSharedMemorySize, 131072);
    cudaFuncSetAttribute(k_fp,        cudaFuncAttributeMaxDynamicSharedMemorySize, 65536);

    k_init<<<1280, 256>>>(points1, fea1, points2, fea2);

    // --- SA1 ---
    k_fps<8><<<NI, 1024, 98304>>>(g_pts, N0, S1, g_fps1, g_l1x);
    k_ballquery<<<dim3(S1 / 256, NI), 256, 131072>>>(g_pts, g_l1x, N0, S1,
                                                     (float)(0.1 * 0.1), g_gidx1);
    k_group_mm<10, 16><<<1024, 256>>>(g_pts, g_l1x, g_fea, g_gidx1, sa1_w0, g_h1a,
                                      N0, S1, NI * S1 * 16);
    run_bn<16>(g_h1a, B_ * S1 * 16, SL_SA1A, sa1_g0, sa1_b0);
    k_dense<16, 32><<<1024, 256>>>(g_h1a, sa1_w1, g_h1b, NI * S1 * 16);
    run_bn<32>(g_h1b, B_ * S1 * 16, SL_SA1B, sa1_g1, sa1_b1);
    k_maxpool<<<2048, 256>>>(g_h1b, g_l1f, NI * S1, 16, 32);

    // --- SA2 ---
    k_fps<4><<<NI, 1024, 49152>>>(g_l1x, S1, S2, g_fps2, g_l2x);
    k_ballquery<<<dim3(S2 / 256, NI), 256, 65536>>>(g_l1x, g_l2x, S1, S2,
                                                    (float)(0.2 * 0.2), g_gidx2);
    k_group_mm<32, 32><<<256, 256>>>(g_l1x, g_l2x, g_l1f, g_gidx2, sa2_w0, g_h2a,
                                     S1, S2, NI * S2 * 16);
    run_bn<32>(g_h2a, B_ * S2 * 16, SL_SA2A, sa2_g0, sa2_b0);
    k_dense<32, 64><<<256, 256>>>(g_h2a, sa2_w1, g_h2b, NI * S2 * 16);
    run_bn<64>(g_h2b, B_ * S2 * 16, SL_SA2B, sa2_g1, sa2_b1);
    k_maxpool<<<1024, 256>>>(g_h2b, g_l2f, NI * S2, 16, 64);

    // --- set_upconv ---
    k_knn<8><<<dim3(S1 / 256, NI), 256, 4 * S2 * 4>>>(g_l2x, g_l1x, S2, S1, g_suidx);
    k_su1<<<512, 256>>>(su1_w1);
    run_bn<32>(g_hsu, B_ * S1 * 8, SL_SU1, su1_g1, su1_b1);
    k_su_cat<<<64, 256>>>();
    k_dense<64, 32><<<64, 256>>>(g_hcat, su1_w2, g_l1n, NI * S1);
    run_bn<32>(g_l1n, B_ * S1, SL_SU2, su1_g2, su1_b2);

    // --- feature propagation ---
    k_fp<<<dim3(N0 / 256, NI), 256, 65536>>>();
    k_dense<42, 32><<<128, 256>>>(g_fph, fp_w, g_l0n, NI * N0);
    run_bn<32>(g_l0n, B_ * N0, SL_FP, fp_g, fp_b);
    run_bn<32>(g_l0n, B_ * N0, SL_BN1, bn1_g, bn1_b);

    // --- final conv + concat ---
    k_final<<<128, 256>>>(conv2_w, conv2_b, (float*)d_out);
}

// round 10
// speedup vs baseline: 1.3811x; 1.3810x over previous
#include <cuda_runtime.h>

// ---------------------------------------------------------------------------
// Problem constants
// ---------------------------------------------------------------------------
constexpr int P_ = 2;           // two pipelines (points1/points2)
constexpr int B_ = 2;           // batch per pipeline
constexpr int NI = P_ * B_;     // 4 independent instances
constexpr int N0 = 8192;        // input points
constexpr int C0 = 10;          // input feature channels
constexpr int S1 = 4096;        // SA1 npoint
constexpr int S2 = 1024;        // SA2 npoint

// ---------------------------------------------------------------------------
// Scratch (static device globals — no allocation allowed)
// ---------------------------------------------------------------------------
__device__ float d_pts [NI * N0 * 3];
__device__ float d_fea [NI * N0 * C0];
__device__ int   d_fps1[NI * S1];
__device__ float d_l1x [NI * S1 * 3];
__device__ int   d_gidx1[NI * S1 * 16];
__device__ float d_h1a [NI * S1 * 16 * 16];
__device__ float d_h1b [NI * S1 * 16 * 32];
__device__ float d_l1f [NI * S1 * 32];
__device__ int   d_fps2[NI * S2];
__device__ float d_l2x [NI * S2 * 3];
__device__ int   d_gidx2[NI * S2 * 16];
__device__ float d_h2a [NI * S2 * 16 * 32];
__device__ float d_h2b [NI * S2 * 16 * 64];
__device__ float d_l2f [NI * S2 * 64];
__device__ int   d_suidx[NI * S1 * 8];
__device__ float d_hsu [NI * S1 * 8 * 32];
__device__ float d_hcat[NI * S1 * 64];
__device__ float d_l1n [NI * S1 * 32];
__device__ float d_fph [NI * N0 * 42];
__device__ float d_l0n [NI * N0 * 32];
__device__ float d_acc [1088];   // BN accumulators for all 8 BN sites

// BN accumulator slot offsets (each slot holds P_*2*C floats)
constexpr int SL_SA1A = 0;     // C=16
constexpr int SL_SA1B = 64;    // C=32
constexpr int SL_SA2A = 192;   // C=32
constexpr int SL_SA2B = 320;   // C=64
constexpr int SL_SU1  = 576;   // C=32
constexpr int SL_SU2  = 704;   // C=32
constexpr int SL_FP   = 832;   // C=32
constexpr int SL_BN1  = 960;   // C=32

// ---------------------------------------------------------------------------
// Helpers
// ---------------------------------------------------------------------------
__device__ __forceinline__ float sumsq3(float x, float y, float z) {
    // strict mul/add — matches XLA elementwise+reduce fusion (no fma)
    return __fadd_rn(__fadd_rn(__fmul_rn(x, x), __fmul_rn(y, y)), __fmul_rn(z, z));
}
__device__ __forceinline__ float expdist(float qx, float qy, float qz, float qq,
                                         float px, float py, float pz, float pp) {
    // dot product via fma chain — matches Eigen dot_general K-loop (fma accumulate)
    float dot = fmaf(qz, pz, fmaf(qy, py, __fmul_rn(qx, px)));
    return __fsub_rn(__fadd_rn(qq, pp), __fmul_rn(2.0f, dot));
}
template <int KK>
__device__ __forceinline__ void topk_insert(float d, int j, float* bd, int* bi) {
    if (d < bd[KK - 1] || (d == bd[KK - 1] && j < bi[KK - 1])) {
        bd[KK - 1] = d; bi[KK - 1] = j;
#pragma unroll
        for (int t = KK - 1; t > 0; t--) {
            if (bd[t] < bd[t - 1] || (bd[t] == bd[t - 1] && bi[t] < bi[t - 1])) {
                float td = bd[t]; bd[t] = bd[t - 1]; bd[t - 1] = td;
                int   ti = bi[t]; bi[t] = bi[t - 1]; bi[t - 1] = ti;
            }
        }
    }
}

// ---------------------------------------------------------------------------
// Init: pack inputs into per-instance buffers, zero BN accumulators
// ---------------------------------------------------------------------------
__global__ void k_init(const float* __restrict__ p1, const float* __restrict__ f1,
                       const float* __restrict__ p2, const float* __restrict__ f2) {
    int i = blockIdx.x * blockDim.x + threadIdx.x;
    if (i < NI * N0 * 3)
        d_pts[i] = (i < B_ * N0 * 3) ? p1[i] : p2[i - B_ * N0 * 3];
    if (i < NI * N0 * C0)
        d_fea[i] = (i < B_ * N0 * C0) ? f1[i] : f2[i - B_ * N0 * C0];
    if (i < 1088) d_acc[i] = 0.0f;
}

// ---------------------------------------------------------------------------
// Farthest point sampling: one 1024-thread block per instance.
// Single barrier per iteration (double-buffered candidates) + HW redux.
// ---------------------------------------------------------------------------
template <int NPT>
__global__ void __launch_bounds__(1024) k_fps(const float* __restrict__ ptsAll,
                                              int N, int npoint,
                                              int* __restrict__ idxAll,
                                              float* __restrict__ nxyzAll) {
    const int T = 1024;
    int inst = blockIdx.x;
    const float* xyz = ptsAll + inst * N * 3;
    int*   idx_out = idxAll + inst * npoint;
    float* nxyz    = nxyzAll + inst * npoint * 3;

    extern __shared__ float4 s4[];          // (x, y, z, 0) per point
    __shared__ unsigned s_rv[2][32];
    __shared__ int      s_ri[2][32];

    int tid = threadIdx.x;
    int lane = tid & 31, wid = tid >> 5;

    float px[NPT], py[NPT], pz[NPT], dd[NPT];
#pragma unroll
    for (int u = 0; u < NPT; u++) {
        int j = tid + u * T;
        px[u] = xyz[3 * j]; py[u] = xyz[3 * j + 1]; pz[u] = xyz[3 * j + 2];
        dd[u] = 1e10f;
        s4[j] = make_float4(px[u], py[u], pz[u], 0.0f);
    }
    if (tid == 0) idx_out[0] = 0;
    __syncthreads();

    float4 c0 = s4[0];
    float cx = c0.x, cy = c0.y, cz = c0.z;
    int buf = 0;

    for (int i = 0; i < npoint - 1; i++) {
        // 1) update running min-dist, find per-thread best (first-index tie-break)
        float bv = -1.0f; int bi = 0;
#pragma unroll
        for (int u = 0; u < NPT; u++) {
            float dx = __fsub_rn(px[u], cx);
            float dy = __fsub_rn(py[u], cy);
            float dz = __fsub_rn(pz[u], cz);
            float d = sumsq3(dx, dy, dz);
            float nd = fminf(dd[u], d);
            dd[u] = nd;
            if (nd > bv) { bv = nd; bi = tid + u * T; }
        }
        // 2) warp reduce via HW redux (distances >= 0, bits order-isomorphic)
        unsigned vb = __float_as_uint(bv);
        unsigned vmax = __reduce_max_sync(0xffffffffu, vb);
        int cand = (vb == vmax) ? bi : 0x7fffffff;
        int imin = __reduce_min_sync(0xffffffffu, cand);
        if (lane == 0) { s_rv[buf][wid] = vmax; s_ri[buf][wid] = imin; }
        __syncthreads();
        // 3) all warps redundantly reduce the 32 warp candidates
        unsigned v2 = s_rv[buf][lane];
        int      i2 = s_ri[buf][lane];
        unsigned vmax2 = __reduce_max_sync(0xffffffffu, v2);
        int cand2 = (v2 == vmax2) ? i2 : 0x7fffffff;
        int bi2 = __reduce_min_sync(0xffffffffu, cand2);
        // 4) broadcast center from smem (no extra barrier; next write is other buffer)
        float4 c = s4[bi2];
        cx = c.x; cy = c.y; cz = c.z;
        if (tid == 0) idx_out[i + 1] = bi2;
        buf ^= 1;
    }
    __syncthreads();
    for (int s = tid; s < npoint; s += T) {
        int id = idx_out[s];
        float4 c = s4[id];
        nxyz[3 * s] = c.x; nxyz[3 * s + 1] = c.y; nxyz[3 * s + 2] = c.z;
    }
}

// ---------------------------------------------------------------------------
// Ball query: first 16 in-range indices (== 16 smallest) + nearest fallback
// smem table packed as float4(x,y,z,|p|^2): one LDS.128 per candidate
// ---------------------------------------------------------------------------
__global__ void k_ballquery(const float* __restrict__ ptsAll, const float* __restrict__ qAll,
                            int N, int S, float r2, int* __restrict__ gidxAll) {
    extern __shared__ float4 s4[];
    int inst = blockIdx.y;
    const float* pts = ptsAll + inst * N * 3;
    for (int j = threadIdx.x; j < N; j += blockDim.x) {
        float x = pts[3 * j], y = pts[3 * j + 1], z = pts[3 * j + 2];
        s4[j] = make_float4(x, y, z, sumsq3(x, y, z));
    }
    __syncthreads();
    int q = blockIdx.x * blockDim.x + threadIdx.x;
    if (q >= S) return;
    const float* nq = qAll + (inst * S + q) * 3;
    float qx = nq[0], qy = nq[1], qz = nq[2];
    float qq = sumsq3(qx, qy, qz);

    int res[16]; int cnt = 0;
    float dmin = 3.402823466e38f; int jmin = 0;
    for (int j = 0; j < N; j++) {
        float4 p = s4[j];
        float d = expdist(qx, qy, qz, qq, p.x, p.y, p.z, p.w);
        if (d < dmin) { dmin = d; jmin = j; }
        if (d <= r2) { res[cnt++] = j; if (cnt == 16) break; }
    }
    int* out = gidxAll + (inst * S + q) * 16;
    if (cnt == 0) {
        for (int k = 0; k < 16; k++) out[k] = jmin;
    } else {
        int f = res[0];
        for (int k = 0; k < 16; k++) out[k] = (k < cnt) ? res[k] : f;
    }
}

// ---------------------------------------------------------------------------
// kNN (k smallest distances, stable tie-break) — set_upconv (k=8)
// ---------------------------------------------------------------------------
template <int KK>
__global__ void k_knn(const float* __restrict__ refAll, const float* __restrict__ qAll,
                      int M, int S, int* __restrict__ outIdx) {
    extern __shared__ float4 s4[];
    int inst = blockIdx.y;
    const float* ref = refAll + inst * M * 3;
    for (int j = threadIdx.x; j < M; j += blockDim.x) {
        float x = ref[3 * j], y = ref[3 * j + 1], z = ref[3 * j + 2];
        s4[j] = make_float4(x, y, z, sumsq3(x, y, z));
    }
    __syncthreads();
    int q = blockIdx.x * blockDim.x + threadIdx.x;
    if (q >= S) return;
    const float* qp = qAll + (inst * S + q) * 3;
    float qx = qp[0], qy = qp[1], qz = qp[2];
    float qq = sumsq3(qx, qy, qz);
    float bd[KK]; int bi[KK];
#pragma unroll
    for (int k = 0; k < KK; k++) { bd[k] = 3.402823466e38f; bi[k] = 0x7fffffff; }
    for (int j = 0; j < M; j++) {
        float4 p = s4[j];
        float d = expdist(qx, qy, qz, qq, p.x, p.y, p.z, p.w);
        topk_insert<KK>(d, j, bd, bi);
    }
    int* o = outIdx + (inst * S + q) * KK;
#pragma unroll
    for (int k = 0; k < KK; k++) o[k] = bi[k];
}

// ---------------------------------------------------------------------------
// SA layer0 matmul with fused grouping: in = [xyz[id]-newxyz, feat[id]]
// ---------------------------------------------------------------------------
template <int CF, int O>
__global__ void k_group_mm(const float* __restrict__ ptsAll, const float* __restrict__ nxyzAll,
                           const float* __restrict__ featAll, const int* __restrict__ gidxAll,
                           const float* __restrict__ w, float* __restrict__ outAll,
                           int N, int S, int rowsTotal) {
    const int CIN = CF + 3;
    __shared__ float sw[O * CIN];
    for (int i = threadIdx.x; i < O * CIN; i += blockDim.x) sw[i] = w[i];
    __syncthreads();
    int g = blockIdx.x * blockDim.x + threadIdx.x;
    if (g >= rowsTotal) return;
    int sk = S * 16;
    int inst = g / sk;
    int rem = g - inst * sk;
    int s = rem >> 4;
    int id = gidxAll[g];
    const float* p = ptsAll + (inst * N + id) * 3;
    const float* nx = nxyzAll + (inst * S + s) * 3;
    float in[CIN];
    in[0] = p[0] - nx[0]; in[1] = p[1] - nx[1]; in[2] = p[2] - nx[2];
    const float* f = featAll + (inst * N + id) * CF;
#pragma unroll
    for (int c = 0; c < CF; c++) in[3 + c] = f[c];
    float* o = outAll + (size_t)g * O;
    for (int oo = 0; oo < O; oo++) {
        float acc = 0.0f;
#pragma unroll
        for (int c = 0; c < CIN; c++) acc = fmaf(in[c], sw[oo * CIN + c], acc);
        o[oo] = acc;
    }
}

// ---------------------------------------------------------------------------
// Dense row matmul
// ---------------------------------------------------------------------------
template <int CIN, int O>
__global__ void k_dense(const float* __restrict__ inAll, const float* __restrict__ w,
                        float* __restrict__ outAll, int rows) {
    __shared__ float sw[O * CIN];
    for (int i = threadIdx.x; i < O * CIN; i += blockDim.x) sw[i] = w[i];
    __syncthreads();
    int g = blockIdx.x * blockDim.x + threadIdx.x;
    if (g >= rows) return;
    float in[CIN];
    const float* src = inAll + (size_t)g * CIN;
#pragma unroll
    for (int c = 0; c < CIN; c++) in[c] = src[c];
    float* o = outAll + (size_t)g * O;
    for (int oo = 0; oo < O; oo++) {
        float acc = 0.0f;
#pragma unroll
        for (int c = 0; c < CIN; c++) acc = fmaf(in[c], sw[oo * CIN + c], acc);
        o[oo] = acc;
    }
}

// ---------------------------------------------------------------------------
// BN reduce (sum, sumsq per channel per pipeline) + apply scale/shift + relu
// ---------------------------------------------------------------------------
template <int C>
__global__ void k_bnreduce(const float* __restrict__ x, int rowsPerP, int slotOff) {
    __shared__ float ss[C], sq[C];
    int tid = threadIdx.x;
    if (tid < C) { ss[tid] = 0.0f; sq[tid] = 0.0f; }
    __syncthreads();
    int p = blockIdx.z;
    const float* base = x + (size_t)p * rowsPerP * C;
    size_t total = (size_t)rowsPerP * C;
    size_t stride = (size_t)gridDim.x * blockDim.x;
    float ls = 0.0f, lq = 0.0f;
    for (size_t e = (size_t)blockIdx.x * blockDim.x + tid; e < total; e += stride) {
        float v = base[e];
        ls += v;
        lq = fmaf(v, v, lq);
    }
    int c = tid & (C - 1);
    atomicAdd(&ss[c], ls);
    atomicAdd(&sq[c], lq);
    __syncthreads();
    if (tid < C) {
        atomicAdd(&d_acc[slotOff + p * 2 * C + tid], ss[tid]);
        atomicAdd(&d_acc[slotOff + p * 2 * C + C + tid], sq[tid]);
    }
}

template <int C>
__global__ void k_bnapply(float* __restrict__ x, int rowsPerP, int slotOff,
                          const float* __restrict__ g, const float* __restrict__ b,
                          float invR) {
    __shared__ float sc[C], sh[C];
    int tid = threadIdx.x;
    if (tid < C) {
        float s = d_acc[slotOff + blockIdx.z * 2 * C + tid];
        float q = d_acc[slotOff + blockIdx.z * 2 * C + C + tid];
        float m = s * invR;
        float v = fmaf(-m, m, q * invR);
        if (v < 0.0f) v = 0.0f;
        float k = rsqrtf(v + 1e-5f) * g[tid];
        sc[tid] = k;
        sh[tid] = b[tid] - m * k;
    }
    __syncthreads();
    float* base = x + (size_t)blockIdx.z * rowsPerP * C;
    size_t total = (size_t)rowsPerP * C;
    size_t e = (size_t)blockIdx.x * blockDim.x + tid;
    if (e < total) {
        int c = tid & (C - 1);
        float y = fmaf(base[e], sc[c], sh[c]);
        base[e] = fmaxf(y, 0.0f);
    }
}

// ---------------------------------------------------------------------------
// Max-pool over K samples
// ---------------------------------------------------------------------------
__global__ void k_maxpool(const float* __restrict__ in, float* __restrict__ out,
                          int Stot, int K, int C) {
    int g = blockIdx.x * blockDim.x + threadIdx.x;
    if (g >= Stot * C) return;
    int s = g / C, c = g - s * C;
    const float* p = in + (size_t)s * K * C + c;
    float m = p[0];
    for (int k = 1; k < K; k++) m = fmaxf(m, p[(size_t)k * C]);
    out[g] = m;
}

// ---------------------------------------------------------------------------
// set_upconv layer1 matmul: in = [l2f[id] (64), l2x[id]-l1x[s] (3)]
// ---------------------------------------------------------------------------
__global__ void k_su1(const float* __restrict__ w) {
    __shared__ float sw[32 * 67];
    for (int i = threadIdx.x; i < 32 * 67; i += blockDim.x) sw[i] = w[i];
    __syncthreads();
    int g = blockIdx.x * blockDim.x + threadIdx.x;  // NI*S1*8 = 131072 exact
    int inst = g >> 15;
    int rem = g & 32767;
    int s = rem >> 3;
    int id = d_suidx[g];
    float in[67];
    const float4* f4 = (const float4*)(d_l2f + ((size_t)inst * S2 + id) * 64);
#pragma unroll
    for (int c = 0; c < 16; c++) {
        float4 v = f4[c];
        in[c * 4] = v.x; in[c * 4 + 1] = v.y; in[c * 4 + 2] = v.z; in[c * 4 + 3] = v.w;
    }
    const float* p2 = d_l2x + ((size_t)inst * S2 + id) * 3;
    const float* p1 = d_l1x + ((size_t)inst * S1 + s) * 3;
    in[64] = p2[0] - p1[0]; in[65] = p2[1] - p1[1]; in[66] = p2[2] - p1[2];
    float* o = d_hsu + (size_t)g * 32;
    for (int oo = 0; oo < 32; oo++) {
        float acc = 0.0f;
#pragma unroll
        for (int c = 0; c < 67; c++) acc = fmaf(in[c], sw[oo * 67 + c], acc);
        o[oo] = acc;
    }
}

// Max over k=8 of hsu, concat with l1f -> hcat (64ch)
__global__ void k_su_cat() {
    int row = blockIdx.x * blockDim.x + threadIdx.x;  // NI*S1 = 16384 exact
    const float* h = d_hsu + (size_t)row * 8 * 32;
    float* o = d_hcat + (size_t)row * 64;
#pragma unroll 4
    for (int c = 0; c < 32; c++) {
        float m = h[c];
        for (int k = 1; k < 8; k++) m = fmaxf(m, h[k * 32 + c]);
        o[c] = m;
    }
    const float* f = d_l1f + (size_t)row * 32;
#pragma unroll 4
    for (int c = 0; c < 32; c++) o[32 + c] = f[c];
}

// ---------------------------------------------------------------------------
// Feature propagation: 3-NN interp of l1n + concat raw features -> fph (42ch)
// ---------------------------------------------------------------------------
__global__ void k_fp() {
    const int M = S1;  // 4096 ref points
    extern __shared__ float4 s4[];
    int inst = blockIdx.y;
    const float* ref = d_l1x + inst * M * 3;
    for (int j = threadIdx.x; j < M; j += blockDim.x) {
        float x = ref[3 * j], y = ref[3 * j + 1], z = ref[3 * j + 2];
        s4[j] = make_float4(x, y, z, sumsq3(x, y, z));
    }
    __syncthreads();
    int q = blockIdx.x * blockDim.x + threadIdx.x;  // S=8192
    const float* qp = d_pts + ((size_t)inst * N0 + q) * 3;
    float qx = qp[0], qy = qp[1], qz = qp[2];
    float qq = sumsq3(qx, qy, qz);
    float bd[3]; int bi[3];
#pragma unroll
    for (int k = 0; k < 3; k++) { bd[k] = 3.402823466e38f; bi[k] = 0x7fffffff; }
    for (int j = 0; j < M; j++) {
        float4 p = s4[j];
        float d = expdist(qx, qy, qz, qq, p.x, p.y, p.z, p.w);
        topk_insert<3>(d, j, bd, bi);
    }
    float w0 = 1.0f / fmaxf(bd[0], 1e-10f);
    float w1 = 1.0f / fmaxf(bd[1], 1e-10f);
    float w2 = 1.0f / fmaxf(bd[2], 1e-10f);
    float s = (w0 + w1) + w2;
    w0 /= s; w1 /= s; w2 /= s;
    const float* f0 = d_l1n + ((size_t)inst * S1 + bi[0]) * 32;
    const float* f1 = d_l1n + ((size_t)inst * S1 + bi[1]) * 32;
    const float* f2 = d_l1n + ((size_t)inst * S1 + bi[2]) * 32;
    float* o = d_fph + ((size_t)inst * N0 + q) * 42;
#pragma unroll 4
    for (int c = 0; c < 32; c++)
        o[c] = f0[c] * w0 + f1[c] * w1 + f2[c] * w2;
    const float* fr = d_fea + ((size_t)inst * N0 + q) * C0;
#pragma unroll
    for (int c = 0; c < C0; c++) o[32 + c] = fr[c];
}

// ---------------------------------------------------------------------------
// Final: sf = x @ conv2_w^T + b; out = concat(pts, sf)  -> (2, B, N, 19)
// ---------------------------------------------------------------------------
__global__ void k_final(const float* __restrict__ w, const float* __restrict__ b,
                        float* __restrict__ out) {
    __shared__ float sw[16 * 32];
    for (int i = threadIdx.x; i < 16 * 32; i += blockDim.x) sw[i] = w[i];
    __syncthreads();
    int g = blockIdx.x * blockDim.x + threadIdx.x;  // NI*N0 = 32768 exact
    float in[32];
    const float* src = d_l0n + (size_t)g * 32;
#pragma unroll
    for (int c = 0; c < 32; c++) in[c] = src[c];
    float* o = out + (size_t)g * 19;
    const float* p = d_pts + (size_t)g * 3;
    o[0] = p[0]; o[1] = p[1]; o[2] = p[2];
    for (int oo = 0; oo < 16; oo++) {
        float acc = 0.0f;
#pragma unroll
        for (int c = 0; c < 32; c++) acc = fmaf(in[c], sw[oo * 32 + c], acc);
        o[3 + oo] = acc + b[oo];
    }
}

// ---------------------------------------------------------------------------
// Host
// ---------------------------------------------------------------------------
template <int C>
static void run_bn(float* buf, int rowsPerP, int slot, const float* g, const float* b) {
    size_t total = (size_t)rowsPerP * C;
    dim3 rg(64, 1, P_);
    k_bnreduce<C><<<rg, 256>>>(buf, rowsPerP, slot);
    dim3 ag((unsigned)((total + 255) / 256), 1, P_);
    k_bnapply<C><<<ag, 256>>>(buf, rowsPerP, slot, g, b, 1.0f / (float)total * (float)C);
}

extern "C" void kernel_launch(void* const* d_in, const int* in_sizes, int n_in,
                              void* d_out, int out_size) {
    const float* points1 = (const float*)d_in[0];
    const float* fea1    = (const float*)d_in[1];
    const float* points2 = (const float*)d_in[2];
    const float* fea2    = (const float*)d_in[3];
    const float* sa1_w0  = (const float*)d_in[4];
    const float* sa1_g0  = (const float*)d_in[5];
    const float* sa1_b0  = (const float*)d_in[6];
    const float* sa1_w1  = (const float*)d_in[7];
    const float* sa1_g1  = (const float*)d_in[8];
    const float* sa1_b1  = (const float*)d_in[9];
    const float* sa2_w0  = (const float*)d_in[10];
    const float* sa2_g0  = (const float*)d_in[11];
    const float* sa2_b0  = (const float*)d_in[12];
    const float* sa2_w1  = (const float*)d_in[13];
    const float* sa2_g1  = (const float*)d_in[14];
    const float* sa2_b1  = (const float*)d_in[15];
    const float* su1_w1  = (const float*)d_in[16];
    const float* su1_g1  = (const float*)d_in[17];
    const float* su1_b1  = (const float*)d_in[18];
    const float* su1_w2  = (const float*)d_in[19];
    const float* su1_g2  = (const float*)d_in[20];
    const float* su1_b2  = (const float*)d_in[21];
    const float* fp_w    = (const float*)d_in[22];
    const float* fp_g    = (const float*)d_in[23];
    const float* fp_b    = (const float*)d_in[24];
    const float* bn1_g   = (const float*)d_in[25];
    const float* bn1_b   = (const float*)d_in[26];
    const float* conv2_w = (const float*)d_in[27];
    const float* conv2_b = (const float*)d_in[28];

    float *g_pts, *g_fea, *g_l1x, *g_l2x, *g_h1a, *g_h1b, *g_l1f, *g_h2a, *g_h2b,
          *g_l2f, *g_hsu, *g_hcat, *g_l1n, *g_fph, *g_l0n;
    int *g_fps1, *g_fps2, *g_gidx1, *g_gidx2, *g_suidx;
    cudaGetSymbolAddress((void**)&g_pts,  d_pts);
    cudaGetSymbolAddress((void**)&g_fea,  d_fea);
    cudaGetSymbolAddress((void**)&g_l1x,  d_l1x);
    cudaGetSymbolAddress((void**)&g_l2x,  d_l2x);
    cudaGetSymbolAddress((void**)&g_h1a,  d_h1a);
    cudaGetSymbolAddress((void**)&g_h1b,  d_h1b);
    cudaGetSymbolAddress((void**)&g_l1f,  d_l1f);
    cudaGetSymbolAddress((void**)&g_h2a,  d_h2a);
    cudaGetSymbolAddress((void**)&g_h2b,  d_h2b);
    cudaGetSymbolAddress((void**)&g_l2f,  d_l2f);
    cudaGetSymbolAddress((void**)&g_hsu,  d_hsu);
    cudaGetSymbolAddress((void**)&g_hcat, d_hcat);
    cudaGetSymbolAddress((void**)&g_l1n,  d_l1n);
    cudaGetSymbolAddress((void**)&g_fph,  d_fph);
    cudaGetSymbolAddress((void**)&g_l0n,  d_l0n);
    cudaGetSymbolAddress((void**)&g_fps1, d_fps1);
    cudaGetSymbolAddress((void**)&g_fps2, d_fps2);
    cudaGetSymbolAddress((void**)&g_gidx1, d_gidx1);
    cudaGetSymbolAddress((void**)&g_gidx2, d_gidx2);
    cudaGetSymbolAddress((void**)&g_suidx, d_suidx);

    cudaFuncSetAttribute(k_fps<8>,    cudaFuncAttributeMaxDynamicSharedMemorySize, 131072);
    cudaFuncSetAttribute(k_fps<4>,    cudaFuncAttributeMaxDynamicSharedMemorySize, 65536);
    cudaFuncSetAttribute(k_ballquery, cudaFuncAttributeMaxDynamicSharedMemorySize, 131072);
    cudaFuncSetAttribute(k_fp,        cudaFuncAttributeMaxDynamicSharedMemorySize, 65536);

    k_init<<<1280, 256>>>(points1, fea1, points2, fea2);

    // --- SA1 ---
    k_fps<8><<<NI, 1024, 131072>>>(g_pts, N0, S1, g_fps1, g_l1x);
    k_ballquery<<<dim3(S1 / 256, NI), 256, 131072>>>(g_pts, g_l1x, N0, S1,
                                                     (float)(0.1 * 0.1), g_gidx1);
    k_group_mm<10, 16><<<1024, 256>>>(g_pts, g_l1x, g_fea, g_gidx1, sa1_w0, g_h1a,
                                      N0, S1, NI * S1 * 16);
    run_bn<16>(g_h1a, B_ * S1 * 16, SL_SA1A, sa1_g0, sa1_b0);
    k_dense<16, 32><<<1024, 256>>>(g_h1a, sa1_w1, g_h1b, NI * S1 * 16);
    run_bn<32>(g_h1b, B_ * S1 * 16, SL_SA1B, sa1_g1, sa1_b1);
    k_maxpool<<<2048, 256>>>(g_h1b, g_l1f, NI * S1, 16, 32);

    // --- SA2 ---
    k_fps<4><<<NI, 1024, 65536>>>(g_l1x, S1, S2, g_fps2, g_l2x);
    k_ballquery<<<dim3(S2 / 256, NI), 256, 65536>>>(g_l1x, g_l2x, S1, S2,
                                                    (float)(0.2 * 0.2), g_gidx2);
    k_group_mm<32, 32><<<256, 256>>>(g_l1x, g_l2x, g_l1f, g_gidx2, sa2_w0, g_h2a,
                                     S1, S2, NI * S2 * 16);
    run_bn<32>(g_h2a, B_ * S2 * 16, SL_SA2A, sa2_g0, sa2_b0);
    k_dense<32, 64><<<256, 256>>>(g_h2a, sa2_w1, g_h2b, NI * S2 * 16);
    run_bn<64>(g_h2b, B_ * S2 * 16, SL_SA2B, sa2_g1, sa2_b1);
    k_maxpool<<<1024, 256>>>(g_h2b, g_l2f, NI * S2, 16, 64);

    // --- set_upconv ---
    k_knn<8><<<dim3(S1 / 256, NI), 256, S2 * 16>>>(g_l2x, g_l1x, S2, S1, g_suidx);
    k_su1<<<512, 256>>>(su1_w1);
    run_bn<32>(g_hsu, B_ * S1 * 8, SL_SU1, su1_g1, su1_b1);
    k_su_cat<<<64, 256>>>();
    k_dense<64, 32><<<64, 256>>>(g_hcat, su1_w2, g_l1n, NI * S1);
    run_bn<32>(g_l1n, B_ * S1, SL_SU2, su1_g2, su1_b2);

    // --- feature propagation ---
    k_fp<<<dim3(N0 / 256, NI), 256, 65536>>>();
    k_dense<42, 32><<<128, 256>>>(g_fph, fp_w, g_l0n, NI * N0);
    run_bn<32>(g_l0n, B_ * N0, SL_FP, fp_g, fp_b);
    run_bn<32>(g_l0n, B_ * N0, SL_BN1, bn1_g, bn1_b);

    // --- final conv + concat ---
    k_final<<<128, 256>>>(conv2_w, conv2_b, (float*)d_out);
}

// round 11
// speedup vs baseline: 1.6635x; 1.2045x over previous
#include <cuda_runtime.h>

// ---------------------------------------------------------------------------
// Problem constants
// ---------------------------------------------------------------------------
constexpr int P_ = 2;           // two pipelines (points1/points2)
constexpr int B_ = 2;           // batch per pipeline
constexpr int NI = P_ * B_;     // 4 independent instances
constexpr int N0 = 8192;        // input points
constexpr int C0 = 10;          // input feature channels
constexpr int S1 = 4096;        // SA1 npoint
constexpr int S2 = 1024;        // SA2 npoint

// ---------------------------------------------------------------------------
// Scratch (static device globals — no allocation allowed)
// ---------------------------------------------------------------------------
__device__ float d_pts [NI * N0 * 3];
__device__ float d_fea [NI * N0 * C0];
__device__ int   d_fps1[NI * S1];
__device__ float d_l1x [NI * S1 * 3];
__device__ int   d_gidx1[NI * S1 * 16];
__device__ float d_h1a [NI * S1 * 16 * 16];
__device__ float d_h1b [NI * S1 * 16 * 32];
__device__ float d_l1f [NI * S1 * 32];
__device__ int   d_fps2[NI * S2];
__device__ float d_l2x [NI * S2 * 3];
__device__ int   d_gidx2[NI * S2 * 16];
__device__ float d_h2a [NI * S2 * 16 * 32];
__device__ float d_h2b [NI * S2 * 16 * 64];
__device__ float d_l2f [NI * S2 * 64];
__device__ int   d_suidx[NI * S1 * 8];
__device__ float d_hsu [NI * S1 * 8 * 32];
__device__ float d_hcat[NI * S1 * 64];
__device__ float d_l1n [NI * S1 * 32];
__device__ float d_fph [NI * N0 * 42];
__device__ float d_l0n [NI * N0 * 32];
__device__ float d_acc [1088];   // BN accumulators for all 8 BN sites

// BN accumulator slot offsets (each slot holds P_*2*C floats)
constexpr int SL_SA1A = 0;     // C=16
constexpr int SL_SA1B = 64;    // C=32
constexpr int SL_SA2A = 192;   // C=32
constexpr int SL_SA2B = 320;   // C=64
constexpr int SL_SU1  = 576;   // C=32
constexpr int SL_SU2  = 704;   // C=32
constexpr int SL_FP   = 832;   // C=32
constexpr int SL_BN1  = 960;   // C=32

// ---------------------------------------------------------------------------
// Helpers
// ---------------------------------------------------------------------------
__device__ __forceinline__ float sumsq3(float x, float y, float z) {
    // strict mul/add — matches XLA elementwise+reduce fusion (no fma)
    return __fadd_rn(__fadd_rn(__fmul_rn(x, x), __fmul_rn(y, y)), __fmul_rn(z, z));
}
__device__ __forceinline__ float expdist(float qx, float qy, float qz, float qq,
                                         float px, float py, float pz, float pp) {
    // dot product via fma chain — matches Eigen dot_general K-loop (fma accumulate)
    float dot = fmaf(qz, pz, fmaf(qy, py, __fmul_rn(qx, px)));
    return __fsub_rn(__fadd_rn(qq, pp), __fmul_rn(2.0f, dot));
}
template <int KK>
__device__ __forceinline__ void topk_insert(float d, int j, float* bd, int* bi) {
    if (d < bd[KK - 1] || (d == bd[KK - 1] && j < bi[KK - 1])) {
        bd[KK - 1] = d; bi[KK - 1] = j;
#pragma unroll
        for (int t = KK - 1; t > 0; t--) {
            if (bd[t] < bd[t - 1] || (bd[t] == bd[t - 1] && bi[t] < bi[t - 1])) {
                float td = bd[t]; bd[t] = bd[t - 1]; bd[t - 1] = td;
                int   ti = bi[t]; bi[t] = bi[t - 1]; bi[t - 1] = ti;
            }
        }
    }
}

// ---- packed f32x2 (Blackwell) — per-lane round-to-nearest, bit-identical to
// scalar __fadd_rn/__fmul_rn per component ----
__device__ __forceinline__ unsigned long long pk2(float lo, float hi) {
    unsigned long long r;
    asm("mov.b64 %0, {%1, %2};" : "=l"(r) : "f"(lo), "f"(hi));
    return r;
}
__device__ __forceinline__ void upk2(unsigned long long v, float& lo, float& hi) {
    asm("mov.b64 {%0, %1}, %2;" : "=f"(lo), "=f"(hi) : "l"(v));
}
__device__ __forceinline__ unsigned long long add2(unsigned long long a, unsigned long long b) {
    unsigned long long r;
    asm("add.rn.f32x2 %0, %1, %2;" : "=l"(r) : "l"(a), "l"(b));
    return r;
}
__device__ __forceinline__ unsigned long long mul2(unsigned long long a, unsigned long long b) {
    unsigned long long r;
    asm("mul.rn.f32x2 %0, %1, %2;" : "=l"(r) : "l"(a), "l"(b));
    return r;
}

// ---------------------------------------------------------------------------
// Init: pack inputs into per-instance buffers, zero BN accumulators
// ---------------------------------------------------------------------------
__global__ void k_init(const float* __restrict__ p1, const float* __restrict__ f1,
                       const float* __restrict__ p2, const float* __restrict__ f2) {
    int i = blockIdx.x * blockDim.x + threadIdx.x;
    if (i < NI * N0 * 3)
        d_pts[i] = (i < B_ * N0 * 3) ? p1[i] : p2[i - B_ * N0 * 3];
    if (i < NI * N0 * C0)
        d_fea[i] = (i < B_ * N0 * C0) ? f1[i] : f2[i - B_ * N0 * C0];
    if (i < 1088) d_acc[i] = 0.0f;
}

// ---------------------------------------------------------------------------
// Farthest point sampling: one 1024-thread block per instance.
// Single barrier per iteration + HW redux + packed f32x2 distance update.
// Distance update per point pair: 3 add.f32x2 + 3 mul.f32x2 (exact rn per lane,
// same associativity as reference sum((p-c)^2) = (x^2+y^2)+z^2).
// ---------------------------------------------------------------------------
template <int NPT>
__global__ void __launch_bounds__(1024) k_fps(const float* __restrict__ ptsAll,
                                              int N, int npoint,
                                              int* __restrict__ idxAll,
                                              float* __restrict__ nxyzAll) {
    const int T = 1024;
    const int NPH = NPT / 2;
    static_assert(NPT % 2 == 0, "NPT must be even");
    int inst = blockIdx.x;
    const float* xyz = ptsAll + inst * N * 3;
    int*   idx_out = idxAll + inst * npoint;
    float* nxyz    = nxyzAll + inst * npoint * 3;

    extern __shared__ float4 s4[];          // (x, y, z, 0) per point
    __shared__ unsigned s_rv[2][32];
    __shared__ int      s_ri[2][32];

    int tid = threadIdx.x;
    int lane = tid & 31, wid = tid >> 5;

    // packed pairs: pair h holds points (tid + 2h*T, tid + (2h+1)*T)
    unsigned long long px2[NPH], py2[NPH], pz2[NPH];
    float dd[NPT];
#pragma unroll
    for (int h = 0; h < NPH; h++) {
        int j0 = tid + (2 * h) * T;
        int j1 = tid + (2 * h + 1) * T;
        float x0 = xyz[3 * j0], y0 = xyz[3 * j0 + 1], z0 = xyz[3 * j0 + 2];
        float x1 = xyz[3 * j1], y1 = xyz[3 * j1 + 1], z1 = xyz[3 * j1 + 2];
        px2[h] = pk2(x0, x1); py2[h] = pk2(y0, y1); pz2[h] = pk2(z0, z1);
        dd[2 * h] = 1e10f; dd[2 * h + 1] = 1e10f;
        s4[j0] = make_float4(x0, y0, z0, 0.0f);
        s4[j1] = make_float4(x1, y1, z1, 0.0f);
    }
    if (tid == 0) idx_out[0] = 0;
    __syncthreads();

    float4 c0 = s4[0];
    float cx = c0.x, cy = c0.y, cz = c0.z;
    int buf = 0;

    for (int i = 0; i < npoint - 1; i++) {
        // packed negated center (p + (-c) rounds identically to p - c)
        unsigned long long ncx = pk2(-cx, -cx);
        unsigned long long ncy = pk2(-cy, -cy);
        unsigned long long ncz = pk2(-cz, -cz);
        float bv = -1.0f; int bi = 0;
#pragma unroll
        for (int h = 0; h < NPH; h++) {
            unsigned long long dx = add2(px2[h], ncx);
            unsigned long long dy = add2(py2[h], ncy);
            unsigned long long dz = add2(pz2[h], ncz);
            unsigned long long s = add2(add2(mul2(dx, dx), mul2(dy, dy)), mul2(dz, dz));
            float d0, d1; upk2(s, d0, d1);
            float nd0 = fminf(dd[2 * h], d0);     dd[2 * h] = nd0;
            if (nd0 > bv) { bv = nd0; bi = tid + (2 * h) * T; }
            float nd1 = fminf(dd[2 * h + 1], d1); dd[2 * h + 1] = nd1;
            if (nd1 > bv) { bv = nd1; bi = tid + (2 * h + 1) * T; }
        }
        // warp reduce via HW redux (distances >= 0, bits order-isomorphic)
        unsigned vb = __float_as_uint(bv);
        unsigned vmax = __reduce_max_sync(0xffffffffu, vb);
        int cand = (vb == vmax) ? bi : 0x7fffffff;
        int imin = __reduce_min_sync(0xffffffffu, cand);
        if (lane == 0) { s_rv[buf][wid] = vmax; s_ri[buf][wid] = imin; }
        __syncthreads();
        // all warps redundantly reduce the 32 warp candidates
        unsigned v2 = s_rv[buf][lane];
        int      i2 = s_ri[buf][lane];
        unsigned vmax2 = __reduce_max_sync(0xffffffffu, v2);
        int cand2 = (v2 == vmax2) ? i2 : 0x7fffffff;
        int bi2 = __reduce_min_sync(0xffffffffu, cand2);
        // broadcast center from smem (no extra barrier; next write is other buffer)
        float4 c = s4[bi2];
        cx = c.x; cy = c.y; cz = c.z;
        if (tid == 0) idx_out[i + 1] = bi2;
        buf ^= 1;
    }
    __syncthreads();
    for (int s = tid; s < npoint; s += T) {
        int id = idx_out[s];
        float4 c = s4[id];
        nxyz[3 * s] = c.x; nxyz[3 * s + 1] = c.y; nxyz[3 * s + 2] = c.z;
    }
}

// ---------------------------------------------------------------------------
// Ball query: first 16 in-range indices (== 16 smallest) + nearest fallback
// smem table packed as float4(x,y,z,|p|^2): one LDS.128 per candidate
// ---------------------------------------------------------------------------
__global__ void k_ballquery(const float* __restrict__ ptsAll, const float* __restrict__ qAll,
                            int N, int S, float r2, int* __restrict__ gidxAll) {
    extern __shared__ float4 s4[];
    int inst = blockIdx.y;
    const float* pts = ptsAll + inst * N * 3;
    for (int j = threadIdx.x; j < N; j += blockDim.x) {
        float x = pts[3 * j], y = pts[3 * j + 1], z = pts[3 * j + 2];
        s4[j] = make_float4(x, y, z, sumsq3(x, y, z));
    }
    __syncthreads();
    int q = blockIdx.x * blockDim.x + threadIdx.x;
    if (q >= S) return;
    const float* nq = qAll + (inst * S + q) * 3;
    float qx = nq[0], qy = nq[1], qz = nq[2];
    float qq = sumsq3(qx, qy, qz);

    int res[16]; int cnt = 0;
    float dmin = 3.402823466e38f; int jmin = 0;
    for (int j = 0; j < N; j++) {
        float4 p = s4[j];
        float d = expdist(qx, qy, qz, qq, p.x, p.y, p.z, p.w);
        if (d < dmin) { dmin = d; jmin = j; }
        if (d <= r2) { res[cnt++] = j; if (cnt == 16) break; }
    }
    int* out = gidxAll + (inst * S + q) * 16;
    if (cnt == 0) {
        for (int k = 0; k < 16; k++) out[k] = jmin;
    } else {
        int f = res[0];
        for (int k = 0; k < 16; k++) out[k] = (k < cnt) ? res[k] : f;
    }
}

// ---------------------------------------------------------------------------
// kNN (k smallest distances, stable tie-break) — set_upconv (k=8)
// ---------------------------------------------------------------------------
template <int KK>
__global__ void k_knn(const float* __restrict__ refAll, const float* __restrict__ qAll,
                      int M, int S, int* __restrict__ outIdx) {
    extern __shared__ float4 s4[];
    int inst = blockIdx.y;
    const float* ref = refAll + inst * M * 3;
    for (int j = threadIdx.x; j < M; j += blockDim.x) {
        float x = ref[3 * j], y = ref[3 * j + 1], z = ref[3 * j + 2];
        s4[j] = make_float4(x, y, z, sumsq3(x, y, z));
    }
    __syncthreads();
    int q = blockIdx.x * blockDim.x + threadIdx.x;
    if (q >= S) return;
    const float* qp = qAll + (inst * S + q) * 3;
    float qx = qp[0], qy = qp[1], qz = qp[2];
    float qq = sumsq3(qx, qy, qz);
    float bd[KK]; int bi[KK];
#pragma unroll
    for (int k = 0; k < KK; k++) { bd[k] = 3.402823466e38f; bi[k] = 0x7fffffff; }
    for (int j = 0; j < M; j++) {
        float4 p = s4[j];
        float d = expdist(qx, qy, qz, qq, p.x, p.y, p.z, p.w);
        topk_insert<KK>(d, j, bd, bi);
    }
    int* o = outIdx + (inst * S + q) * KK;
#pragma unroll
    for (int k = 0; k < KK; k++) o[k] = bi[k];
}

// ---------------------------------------------------------------------------
// SA layer0 matmul with fused grouping: in = [xyz[id]-newxyz, feat[id]]
// ---------------------------------------------------------------------------
template <int CF, int O>
__global__ void k_group_mm(const float* __restrict__ ptsAll, const float* __restrict__ nxyzAll,
                           const float* __restrict__ featAll, const int* __restrict__ gidxAll,
                           const float* __restrict__ w, float* __restrict__ outAll,
                           int N, int S, int rowsTotal) {
    const int CIN = CF + 3;
    __shared__ float sw[O * CIN];
    for (int i = threadIdx.x; i < O * CIN; i += blockDim.x) sw[i] = w[i];
    __syncthreads();
    int g = blockIdx.x * blockDim.x + threadIdx.x;
    if (g >= rowsTotal) return;
    int sk = S * 16;
    int inst = g / sk;
    int rem = g - inst * sk;
    int s = rem >> 4;
    int id = gidxAll[g];
    const float* p = ptsAll + (inst * N + id) * 3;
    const float* nx = nxyzAll + (inst * S + s) * 3;
    float in[CIN];
    in[0] = p[0] - nx[0]; in[1] = p[1] - nx[1]; in[2] = p[2] - nx[2];
    const float* f = featAll + (inst * N + id) * CF;
#pragma unroll
    for (int c = 0; c < CF; c++) in[3 + c] = f[c];
    float* o = outAll + (size_t)g * O;
    for (int oo = 0; oo < O; oo++) {
        float acc = 0.0f;
#pragma unroll
        for (int c = 0; c < CIN; c++) acc = fmaf(in[c], sw[oo * CIN + c], acc);
        o[oo] = acc;
    }
}

// ---------------------------------------------------------------------------
// Dense row matmul
// ---------------------------------------------------------------------------
template <int CIN, int O>
__global__ void k_dense(const float* __restrict__ inAll, const float* __restrict__ w,
                        float* __restrict__ outAll, int rows) {
    __shared__ float sw[O * CIN];
    for (int i = threadIdx.x; i < O * CIN; i += blockDim.x) sw[i] = w[i];
    __syncthreads();
    int g = blockIdx.x * blockDim.x + threadIdx.x;
    if (g >= rows) return;
    float in[CIN];
    const float* src = inAll + (size_t)g * CIN;
#pragma unroll
    for (int c = 0; c < CIN; c++) in[c] = src[c];
    float* o = outAll + (size_t)g * O;
    for (int oo = 0; oo < O; oo++) {
        float acc = 0.0f;
#pragma unroll
        for (int c = 0; c < CIN; c++) acc = fmaf(in[c], sw[oo * CIN + c], acc);
        o[oo] = acc;
    }
}

// ---------------------------------------------------------------------------
// BN reduce (sum, sumsq per channel per pipeline) + apply scale/shift + relu
// ---------------------------------------------------------------------------
template <int C>
__global__ void k_bnreduce(const float* __restrict__ x, int rowsPerP, int slotOff) {
    __shared__ float ss[C], sq[C];
    int tid = threadIdx.x;
    if (tid < C) { ss[tid] = 0.0f; sq[tid] = 0.0f; }
    __syncthreads();
    int p = blockIdx.z;
    const float* base = x + (size_t)p * rowsPerP * C;
    size_t total = (size_t)rowsPerP * C;
    size_t stride = (size_t)gridDim.x * blockDim.x;
    float ls = 0.0f, lq = 0.0f;
    for (size_t e = (size_t)blockIdx.x * blockDim.x + tid; e < total; e += stride) {
        float v = base[e];
        ls += v;
        lq = fmaf(v, v, lq);
    }
    int c = tid & (C - 1);
    atomicAdd(&ss[c], ls);
    atomicAdd(&sq[c], lq);
    __syncthreads();
    if (tid < C) {
        atomicAdd(&d_acc[slotOff + p * 2 * C + tid], ss[tid]);
        atomicAdd(&d_acc[slotOff + p * 2 * C + C + tid], sq[tid]);
    }
}

template <int C>
__global__ void k_bnapply(float* __restrict__ x, int rowsPerP, int slotOff,
                          const float* __restrict__ g, const float* __restrict__ b,
                          float invR) {
    __shared__ float sc[C], sh[C];
    int tid = threadIdx.x;
    if (tid < C) {
        float s = d_acc[slotOff + blockIdx.z * 2 * C + tid];
        float q = d_acc[slotOff + blockIdx.z * 2 * C + C + tid];
        float m = s * invR;
        float v = fmaf(-m, m, q * invR);
        if (v < 0.0f) v = 0.0f;
        float k = rsqrtf(v + 1e-5f) * g[tid];
        sc[tid] = k;
        sh[tid] = b[tid] - m * k;
    }
    __syncthreads();
    float* base = x + (size_t)blockIdx.z * rowsPerP * C;
    size_t total = (size_t)rowsPerP * C;
    size_t e = (size_t)blockIdx.x * blockDim.x + tid;
    if (e < total) {
        int c = tid & (C - 1);
        float y = fmaf(base[e], sc[c], sh[c]);
        base[e] = fmaxf(y, 0.0f);
    }
}

// ---------------------------------------------------------------------------
// Max-pool over K samples
// ---------------------------------------------------------------------------
__global__ void k_maxpool(const float* __restrict__ in, float* __restrict__ out,
                          int Stot, int K, int C) {
    int g = blockIdx.x * blockDim.x + threadIdx.x;
    if (g >= Stot * C) return;
    int s = g / C, c = g - s * C;
    const float* p = in + (size_t)s * K * C + c;
    float m = p[0];
    for (int k = 1; k < K; k++) m = fmaxf(m, p[(size_t)k * C]);
    out[g] = m;
}

// ---------------------------------------------------------------------------
// set_upconv layer1 matmul: in = [l2f[id] (64), l2x[id]-l1x[s] (3)]
// ---------------------------------------------------------------------------
__global__ void k_su1(const float* __restrict__ w) {
    __shared__ float sw[32 * 67];
    for (int i = threadIdx.x; i < 32 * 67; i += blockDim.x) sw[i] = w[i];
    __syncthreads();
    int g = blockIdx.x * blockDim.x + threadIdx.x;  // NI*S1*8 = 131072 exact
    int inst = g >> 15;
    int rem = g & 32767;
    int s = rem >> 3;
    int id = d_suidx[g];
    float in[67];
    const float4* f4 = (const float4*)(d_l2f + ((size_t)inst * S2 + id) * 64);
#pragma unroll
    for (int c = 0; c < 16; c++) {
        float4 v = f4[c];
        in[c * 4] = v.x; in[c * 4 + 1] = v.y; in[c * 4 + 2] = v.z; in[c * 4 + 3] = v.w;
    }
    const float* p2 = d_l2x + ((size_t)inst * S2 + id) * 3;
    const float* p1 = d_l1x + ((size_t)inst * S1 + s) * 3;
    in[64] = p2[0] - p1[0]; in[65] = p2[1] - p1[1]; in[66] = p2[2] - p1[2];
    float* o = d_hsu + (size_t)g * 32;
    for (int oo = 0; oo < 32; oo++) {
        float acc = 0.0f;
#pragma unroll
        for (int c = 0; c < 67; c++) acc = fmaf(in[c], sw[oo * 67 + c], acc);
        o[oo] = acc;
    }
}

// Max over k=8 of hsu, concat with l1f -> hcat (64ch)
__global__ void k_su_cat() {
    int row = blockIdx.x * blockDim.x + threadIdx.x;  // NI*S1 = 16384 exact
    const float* h = d_hsu + (size_t)row * 8 * 32;
    float* o = d_hcat + (size_t)row * 64;
#pragma unroll 4
    for (int c = 0; c < 32; c++) {
        float m = h[c];
        for (int k = 1; k < 8; k++) m = fmaxf(m, h[k * 32 + c]);
        o[c] = m;
    }
    const float* f = d_l1f + (size_t)row * 32;
#pragma unroll 4
    for (int c = 0; c < 32; c++) o[32 + c] = f[c];
}

// ---------------------------------------------------------------------------
// Feature propagation: 3-NN interp of l1n + concat raw features -> fph (42ch)
// ---------------------------------------------------------------------------
__global__ void k_fp() {
    const int M = S1;  // 4096 ref points
    extern __shared__ float4 s4[];
    int inst = blockIdx.y;
    const float* ref = d_l1x + inst * M * 3;
    for (int j = threadIdx.x; j < M; j += blockDim.x) {
        float x = ref[3 * j], y = ref[3 * j + 1], z = ref[3 * j + 2];
        s4[j] = make_float4(x, y, z, sumsq3(x, y, z));
    }
    __syncthreads();
    int q = blockIdx.x * blockDim.x + threadIdx.x;  // S=8192
    const float* qp = d_pts + ((size_t)inst * N0 + q) * 3;
    float qx = qp[0], qy = qp[1], qz = qp[2];
    float qq = sumsq3(qx, qy, qz);
    float bd[3]; int bi[3];
#pragma unroll
    for (int k = 0; k < 3; k++) { bd[k] = 3.402823466e38f; bi[k] = 0x7fffffff; }
    for (int j = 0; j < M; j++) {
        float4 p = s4[j];
        float d = expdist(qx, qy, qz, qq, p.x, p.y, p.z, p.w);
        topk_insert<3>(d, j, bd, bi);
    }
    float w0 = 1.0f / fmaxf(bd[0], 1e-10f);
    float w1 = 1.0f / fmaxf(bd[1], 1e-10f);
    float w2 = 1.0f / fmaxf(bd[2], 1e-10f);
    float s = (w0 + w1) + w2;
    w0 /= s; w1 /= s; w2 /= s;
    const float* f0 = d_l1n + ((size_t)inst * S1 + bi[0]) * 32;
    const float* f1 = d_l1n + ((size_t)inst * S1 + bi[1]) * 32;
    const float* f2 = d_l1n + ((size_t)inst * S1 + bi[2]) * 32;
    float* o = d_fph + ((size_t)inst * N0 + q) * 42;
#pragma unroll 4
    for (int c = 0; c < 32; c++)
        o[c] = f0[c] * w0 + f1[c] * w1 + f2[c] * w2;
    const float* fr = d_fea + ((size_t)inst * N0 + q) * C0;
#pragma unroll
    for (int c = 0; c < C0; c++) o[32 + c] = fr[c];
}

// ---------------------------------------------------------------------------
// Final: sf = x @ conv2_w^T + b; out = concat(pts, sf)  -> (2, B, N, 19)
// ---------------------------------------------------------------------------
__global__ void k_final(const float* __restrict__ w, const float* __restrict__ b,
                        float* __restrict__ out) {
    __shared__ float sw[16 * 32];
    for (int i = threadIdx.x; i < 16 * 32; i += blockDim.x) sw[i] = w[i];
    __syncthreads();
    int g = blockIdx.x * blockDim.x + threadIdx.x;  // NI*N0 = 32768 exact
    float in[32];
    const float* src = d_l0n + (size_t)g * 32;
#pragma unroll
    for (int c = 0; c < 32; c++) in[c] = src[c];
    float* o = out + (size_t)g * 19;
    const float* p = d_pts + (size_t)g * 3;
    o[0] = p[0]; o[1] = p[1]; o[2] = p[2];
    for (int oo = 0; oo < 16; oo++) {
        float acc = 0.0f;
#pragma unroll
        for (int c = 0; c < 32; c++) acc = fmaf(in[c], sw[oo * 32 + c], acc);
        o[3 + oo] = acc + b[oo];
    }
}

// ---------------------------------------------------------------------------
// Host
// ---------------------------------------------------------------------------
template <int C>
static void run_bn(float* buf, int rowsPerP, int slot, const float* g, const float* b) {
    size_t total = (size_t)rowsPerP * C;
    dim3 rg(64, 1, P_);
    k_bnreduce<C><<<rg, 256>>>(buf, rowsPerP, slot);
    dim3 ag((unsigned)((total + 255) / 256), 1, P_);
    k_bnapply<C><<<ag, 256>>>(buf, rowsPerP, slot, g, b, 1.0f / (float)total * (float)C);
}

extern "C" void kernel_launch(void* const* d_in, const int* in_sizes, int n_in,
                              void* d_out, int out_size) {
    const float* points1 = (const float*)d_in[0];
    const float* fea1    = (const float*)d_in[1];
    const float* points2 = (const float*)d_in[2];
    const float* fea2    = (const float*)d_in[3];
    const float* sa1_w0  = (const float*)d_in[4];
    const float* sa1_g0  = (const float*)d_in[5];
    const float* sa1_b0  = (const float*)d_in[6];
    const float* sa1_w1  = (const float*)d_in[7];
    const float* sa1_g1  = (const float*)d_in[8];
    const float* sa1_b1  = (const float*)d_in[9];
    const float* sa2_w0  = (const float*)d_in[10];
    const float* sa2_g0  = (const float*)d_in[11];
    const float* sa2_b0  = (const float*)d_in[12];
    const float* sa2_w1  = (const float*)d_in[13];
    const float* sa2_g1  = (const float*)d_in[14];
    const float* sa2_b1  = (const float*)d_in[15];
    const float* su1_w1  = (const float*)d_in[16];
    const float* su1_g1  = (const float*)d_in[17];
    const float* su1_b1  = (const float*)d_in[18];
    const float* su1_w2  = (const float*)d_in[19];
    const float* su1_g2  = (const float*)d_in[20];
    const float* su1_b2  = (const float*)d_in[21];
    const float* fp_w    = (const float*)d_in[22];
    const float* fp_g    = (const float*)d_in[23];
    const float* fp_b    = (const float*)d_in[24];
    const float* bn1_g   = (const float*)d_in[25];
    const float* bn1_b   = (const float*)d_in[26];
    const float* conv2_w = (const float*)d_in[27];
    const float* conv2_b = (const float*)d_in[28];

    float *g_pts, *g_fea, *g_l1x, *g_l2x, *g_h1a, *g_h1b, *g_l1f, *g_h2a, *g_h2b,
          *g_l2f, *g_hsu, *g_hcat, *g_l1n, *g_fph, *g_l0n;
    int *g_fps1, *g_fps2, *g_gidx1, *g_gidx2, *g_suidx;
    cudaGetSymbolAddress((void**)&g_pts,  d_pts);
    cudaGetSymbolAddress((void**)&g_fea,  d_fea);
    cudaGetSymbolAddress((void**)&g_l1x,  d_l1x);
    cudaGetSymbolAddress((void**)&g_l2x,  d_l2x);
    cudaGetSymbolAddress((void**)&g_h1a,  d_h1a);
    cudaGetSymbolAddress((void**)&g_h1b,  d_h1b);
    cudaGetSymbolAddress((void**)&g_l1f,  d_l1f);
    cudaGetSymbolAddress((void**)&g_h2a,  d_h2a);
    cudaGetSymbolAddress((void**)&g_h2b,  d_h2b);
    cudaGetSymbolAddress((void**)&g_l2f,  d_l2f);
    cudaGetSymbolAddress((void**)&g_hsu,  d_hsu);
    cudaGetSymbolAddress((void**)&g_hcat, d_hcat);
    cudaGetSymbolAddress((void**)&g_l1n,  d_l1n);
    cudaGetSymbolAddress((void**)&g_fph,  d_fph);
    cudaGetSymbolAddress((void**)&g_l0n,  d_l0n);
    cudaGetSymbolAddress((void**)&g_fps1, d_fps1);
    cudaGetSymbolAddress((void**)&g_fps2, d_fps2);
    cudaGetSymbolAddress((void**)&g_gidx1, d_gidx1);
    cudaGetSymbolAddress((void**)&g_gidx2, d_gidx2);
    cudaGetSymbolAddress((void**)&g_suidx, d_suidx);

    cudaFuncSetAttribute(k_fps<8>,    cudaFuncAttributeMaxDynamicSharedMemorySize, 131072);
    cudaFuncSetAttribute(k_fps<4>,    cudaFuncAttributeMaxDynamicSharedMemorySize, 65536);
    cudaFuncSetAttribute(k_ballquery, cudaFuncAttributeMaxDynamicSharedMemorySize, 131072);
    cudaFuncSetAttribute(k_fp,        cudaFuncAttributeMaxDynamicSharedMemorySize, 65536);

    k_init<<<1280, 256>>>(points1, fea1, points2, fea2);

    // --- SA1 ---
    k_fps<8><<<NI, 1024, 131072>>>(g_pts, N0, S1, g_fps1, g_l1x);
    k_ballquery<<<dim3(S1 / 256, NI), 256, 131072>>>(g_pts, g_l1x, N0, S1,
                                                     (float)(0.1 * 0.1), g_gidx1);
    k_group_mm<10, 16><<<1024, 256>>>(g_pts, g_l1x, g_fea, g_gidx1, sa1_w0, g_h1a,
                                      N0, S1, NI * S1 * 16);
    run_bn<16>(g_h1a, B_ * S1 * 16, SL_SA1A, sa1_g0, sa1_b0);
    k_dense<16, 32><<<1024, 256>>>(g_h1a, sa1_w1, g_h1b, NI * S1 * 16);
    run_bn<32>(g_h1b, B_ * S1 * 16, SL_SA1B, sa1_g1, sa1_b1);
    k_maxpool<<<2048, 256>>>(g_h1b, g_l1f, NI * S1, 16, 32);

    // --- SA2 ---
    k_fps<4><<<NI, 1024, 65536>>>(g_l1x, S1, S2, g_fps2, g_l2x);
    k_ballquery<<<dim3(S2 / 256, NI), 256, 65536>>>(g_l1x, g_l2x, S1, S2,
                                                    (float)(0.2 * 0.2), g_gidx2);
    k_group_mm<32, 32><<<256, 256>>>(g_l1x, g_l2x, g_l1f, g_gidx2, sa2_w0, g_h2a,
                                     S1, S2, NI * S2 * 16);
    run_bn<32>(g_h2a, B_ * S2 * 16, SL_SA2A, sa2_g0, sa2_b0);
    k_dense<32, 64><<<256, 256>>>(g_h2a, sa2_w1, g_h2b, NI * S2 * 16);
    run_bn<64>(g_h2b, B_ * S2 * 16, SL_SA2B, sa2_g1, sa2_b1);
    k_maxpool<<<1024, 256>>>(g_h2b, g_l2f, NI * S2, 16, 64);

    // --- set_upconv ---
    k_knn<8><<<dim3(S1 / 256, NI), 256, S2 * 16>>>(g_l2x, g_l1x, S2, S1, g_suidx);
    k_su1<<<512, 256>>>(su1_w1);
    run_bn<32>(g_hsu, B_ * S1 * 8, SL_SU1, su1_g1, su1_b1);
    k_su_cat<<<64, 256>>>();
    k_dense<64, 32><<<64, 256>>>(g_hcat, su1_w2, g_l1n, NI * S1);
    run_bn<32>(g_l1n, B_ * S1, SL_SU2, su1_g2, su1_b2);

    // --- feature propagation ---
    k_fp<<<dim3(N0 / 256, NI), 256, 65536>>>();
    k_dense<42, 32><<<128, 256>>>(g_fph, fp_w, g_l0n, NI * N0);
    run_bn<32>(g_l0n, B_ * N0, SL_FP, fp_g, fp_b);
    run_bn<32>(g_l0n, B_ * N0, SL_BN1, bn1_g, bn1_b);

    // --- final conv + concat ---
    k_final<<<128, 256>>>(conv2_w, conv2_b, (float*)d_out);
}